// round 3
// baseline (speedup 1.0000x reference)
#include <cuda_runtime.h>
#include <cstdint>

#define E_TOTAL 800000
#define N_TOTAL 50000
#define TILE 64
#define NTHREADS 256

// Shared memory layout (in floats)
#define SA_PITCH 200   // 192 cols max, padded
#define SB_PITCH 136   // 128 cols, padded
#define OFF_SA   0
#define OFF_SB   (OFF_SA + 64*SA_PITCH)
#define OFF_SW   (OFF_SB + 64*SB_PITCH)
#define OFF_BIAS (OFF_SW + 192*128)
#define OFF_IDX  (OFF_BIAS + 128)           // 128 ints (row[64], col[64])
#define SMEM_FLOATS (OFF_IDX + 128)
#define SMEM_BYTES (SMEM_FLOATS * 4)

// scatter-add accumulator (no cudaMalloc allowed -> device global)
__device__ float g_msg[N_TOTAL * 64];
__device__ int   g_idx_is64;   // 1 if edge_index is int64, 0 if int32

__global__ void zero_msg_kernel() {
    int i = blockIdx.x * blockDim.x + threadIdx.x;
    if (i < N_TOTAL * 64) g_msg[i] = 0.0f;
}

// Sniff edge_index dtype: valid int64 indices (< 50000) have zero high words.
// For int32 data reinterpreted as int64, high words contain other random
// indices -> almost surely nonzero within 1024 samples.
__global__ void sniff_idx_kernel(const unsigned int* __restrict__ raw) {
    // raw viewed as uint32 pairs; check high word of first 1024 "int64" entries
    if (threadIdx.x == 0) {
        int is64 = 1;
        for (int i = 0; i < 1024; i++) {
            if (raw[2 * i + 1] != 0u) { is64 = 0; break; }
        }
        g_idx_is64 = is64;
    }
}

__device__ __forceinline__ void load_wb(float* sW, const float* __restrict__ W, int nw,
                                        float* sBias, const float* __restrict__ B, int nb,
                                        int tid) {
    const float4* src = (const float4*)W;
    float4* dst = (float4*)sW;
    int n4 = nw >> 2;
    for (int i = tid; i < n4; i += NTHREADS) dst[i] = src[i];
    for (int i = tid; i < nb; i += NTHREADS) sBias[i] = B[i];
}

// One MLP layer: sOut[r][c] = (relu)(sum_k sIn[r][k] * sW[k][c] + bias[c])
// 64 rows, OUTC cols. Thread micro-tile: 8 rows (ty+8i) x NJ cols (tx+32j).
template<int K, int OUTC, bool RELU>
__device__ __forceinline__ void mlp_layer(
    const float* __restrict__ sIn, int inPitch,
    float* __restrict__ sOut, int outPitch,
    const float* __restrict__ sW, const float* __restrict__ sBias,
    int tx, int ty)
{
    constexpr int NJ = OUTC / 32;
    float acc[8][NJ];
#pragma unroll
    for (int i = 0; i < 8; i++)
#pragma unroll
        for (int j = 0; j < NJ; j++)
            acc[i][j] = sBias[tx + 32 * j];

#pragma unroll 4
    for (int k = 0; k < K; k++) {
        float a[8];
#pragma unroll
        for (int i = 0; i < 8; i++) a[i] = sIn[(ty + 8 * i) * inPitch + k];  // broadcast
#pragma unroll
        for (int j = 0; j < NJ; j++) {
            float w = sW[k * OUTC + tx + 32 * j];  // conflict-free
#pragma unroll
            for (int i = 0; i < 8; i++) acc[i][j] = fmaf(a[i], w, acc[i][j]);
        }
    }
#pragma unroll
    for (int i = 0; i < 8; i++)
#pragma unroll
        for (int j = 0; j < NJ; j++) {
            float v = acc[i][j];
            if (RELU) v = fmaxf(v, 0.0f);
            sOut[(ty + 8 * i) * outPitch + tx + 32 * j] = v;
        }
}

// Final 128->64 layer, result kept in regs for the caller's epilogue.
__device__ __forceinline__ void mlp_final(
    const float* __restrict__ sIn, int inPitch,
    const float* __restrict__ sW, const float* __restrict__ sBias,
    int tx, int ty, float acc[8][2])
{
#pragma unroll
    for (int i = 0; i < 8; i++)
#pragma unroll
        for (int j = 0; j < 2; j++)
            acc[i][j] = sBias[tx + 32 * j];
#pragma unroll 4
    for (int k = 0; k < 128; k++) {
        float a[8];
#pragma unroll
        for (int i = 0; i < 8; i++) a[i] = sIn[(ty + 8 * i) * inPitch + k];
#pragma unroll
        for (int j = 0; j < 2; j++) {
            float w = sW[k * 64 + tx + 32 * j];
#pragma unroll
            for (int i = 0; i < 8; i++) acc[i][j] = fmaf(a[i], w, acc[i][j]);
        }
    }
}

__global__ void __launch_bounds__(NTHREADS, 1)
edge_kernel(const float* __restrict__ h,
            const void* __restrict__ eidx_raw,
            const float* __restrict__ eattr,
            const float* __restrict__ W0, const float* __restrict__ B0,
            const float* __restrict__ W1, const float* __restrict__ B1,
            const float* __restrict__ W2, const float* __restrict__ B2,
            const float* __restrict__ W3, const float* __restrict__ B3,
            float* __restrict__ edge_out)
{
    extern __shared__ float smem[];
    float* sA    = smem + OFF_SA;
    float* sB    = smem + OFF_SB;
    float* sW    = smem + OFF_SW;
    float* sBias = smem + OFF_BIAS;
    int*   sRow  = (int*)(smem + OFF_IDX);
    int*   sCol  = sRow + 64;

    const int tid = threadIdx.x;
    const int tx = tid & 31, ty = tid >> 5;
    const int e0 = blockIdx.x * TILE;

    if (tid < 64) {
        if (g_idx_is64) {
            const long long* e64 = (const long long*)eidx_raw;
            sRow[tid] = (int)e64[e0 + tid];
            sCol[tid] = (int)e64[E_TOTAL + e0 + tid];
        } else {
            const int* e32 = (const int*)eidx_raw;
            sRow[tid] = e32[e0 + tid];
            sCol[tid] = e32[E_TOTAL + e0 + tid];
        }
    }
    load_wb(sW, W0, 192 * 128, sBias, B0, 128, tid);
    __syncthreads();

    // Gather edge_in = [h[row] | h[col] | edge_attr], 192 floats = 48 float4 per row
    for (int idx = tid; idx < 64 * 48; idx += NTHREADS) {
        int r = idx / 48, q = idx - r * 48;
        float4 v;
        if (q < 16)      v = ((const float4*)h)[(size_t)sRow[r] * 16 + q];
        else if (q < 32) v = ((const float4*)h)[(size_t)sCol[r] * 16 + (q - 16)];
        else             v = ((const float4*)eattr)[(size_t)(e0 + r) * 16 + (q - 32)];
        ((float4*)(sA + r * SA_PITCH))[q] = v;
    }
    __syncthreads();

    mlp_layer<192, 128, true>(sA, SA_PITCH, sB, SB_PITCH, sW, sBias, tx, ty);
    __syncthreads();
    load_wb(sW, W1, 128 * 128, sBias, B1, 128, tid);
    __syncthreads();
    mlp_layer<128, 128, true>(sB, SB_PITCH, sA, SA_PITCH, sW, sBias, tx, ty);
    __syncthreads();
    load_wb(sW, W2, 128 * 128, sBias, B2, 128, tid);
    __syncthreads();
    mlp_layer<128, 128, true>(sA, SA_PITCH, sB, SB_PITCH, sW, sBias, tx, ty);
    __syncthreads();
    load_wb(sW, W3, 128 * 64, sBias, B3, 64, tid);
    __syncthreads();

    float acc[8][2];
    mlp_final(sB, SB_PITCH, sW, sBias, tx, ty, acc);

#pragma unroll
    for (int i = 0; i < 8; i++) {
        int r = ty + 8 * i;
        int col = sCol[r];
#pragma unroll
        for (int j = 0; j < 2; j++) {
            int c = tx + 32 * j;
            float v = acc[i][j];
            edge_out[(size_t)(e0 + r) * 64 + c] = v;
            atomicAdd(&g_msg[(size_t)col * 64 + c], v);
        }
    }
}

__global__ void __launch_bounds__(NTHREADS, 1)
node_kernel(const float* __restrict__ h,
            const float* __restrict__ W0, const float* __restrict__ B0,
            const float* __restrict__ W1, const float* __restrict__ B1,
            const float* __restrict__ W2, const float* __restrict__ B2,
            const float* __restrict__ W3, const float* __restrict__ B3,
            float* __restrict__ h_out)
{
    extern __shared__ float smem[];
    float* sA    = smem + OFF_SA;
    float* sB    = smem + OFF_SB;
    float* sW    = smem + OFF_SW;
    float* sBias = smem + OFF_BIAS;

    const int tid = threadIdx.x;
    const int tx = tid & 31, ty = tid >> 5;
    const int n0 = blockIdx.x * TILE;

    load_wb(sW, W0, 128 * 128, sBias, B0, 128, tid);

    // Gather node_in = [h[n] | msg[n]], 128 floats = 32 float4 per row
    for (int idx = tid; idx < 64 * 32; idx += NTHREADS) {
        int r = idx / 32, q = idx - r * 32;
        int n = n0 + r;
        float4 v = make_float4(0.f, 0.f, 0.f, 0.f);
        if (n < N_TOTAL) {
            if (q < 16) v = ((const float4*)h)[(size_t)n * 16 + q];
            else        v = ((const float4*)g_msg)[(size_t)n * 16 + (q - 16)];
        }
        ((float4*)(sA + r * SA_PITCH))[q] = v;
    }
    __syncthreads();

    mlp_layer<128, 128, true>(sA, SA_PITCH, sB, SB_PITCH, sW, sBias, tx, ty);
    __syncthreads();
    load_wb(sW, W1, 128 * 128, sBias, B1, 128, tid);
    __syncthreads();
    mlp_layer<128, 128, true>(sB, SB_PITCH, sA, SA_PITCH, sW, sBias, tx, ty);
    __syncthreads();
    load_wb(sW, W2, 128 * 128, sBias, B2, 128, tid);
    __syncthreads();
    mlp_layer<128, 128, true>(sA, SA_PITCH, sB, SB_PITCH, sW, sBias, tx, ty);
    __syncthreads();
    load_wb(sW, W3, 128 * 64, sBias, B3, 64, tid);
    __syncthreads();

    float acc[8][2];
    mlp_final(sB, SB_PITCH, sW, sBias, tx, ty, acc);

#pragma unroll
    for (int i = 0; i < 8; i++) {
        int n = n0 + ty + 8 * i;
        if (n < N_TOTAL) {
#pragma unroll
            for (int j = 0; j < 2; j++)
                h_out[(size_t)n * 64 + tx + 32 * j] = acc[i][j];
        }
    }
}

extern "C" void kernel_launch(void* const* d_in, const int* in_sizes, int n_in,
                              void* d_out, int out_size)
{
    const float* h     = (const float*)d_in[0];
    const void*  eidx  = d_in[1];                  // int32 or int64, sniffed on device
    const float* eattr = (const float*)d_in[2];
    // dict order interleaves: ew_i, eb_i, nw_i, nb_i for i in 0..3
    const float* ew0 = (const float*)d_in[3],  *eb0 = (const float*)d_in[4];
    const float* nw0 = (const float*)d_in[5],  *nb0 = (const float*)d_in[6];
    const float* ew1 = (const float*)d_in[7],  *eb1 = (const float*)d_in[8];
    const float* nw1 = (const float*)d_in[9],  *nb1 = (const float*)d_in[10];
    const float* ew2 = (const float*)d_in[11], *eb2 = (const float*)d_in[12];
    const float* nw2 = (const float*)d_in[13], *nb2 = (const float*)d_in[14];
    const float* ew3 = (const float*)d_in[15], *eb3 = (const float*)d_in[16];
    const float* nw3 = (const float*)d_in[17], *nb3 = (const float*)d_in[18];

    float* out      = (float*)d_out;
    float* h_out    = out;                        // [50000, 64]
    float* edge_out = out + (size_t)N_TOTAL * 64; // [800000, 64]

    cudaFuncSetAttribute(edge_kernel, cudaFuncAttributeMaxDynamicSharedMemorySize, SMEM_BYTES);
    cudaFuncSetAttribute(node_kernel, cudaFuncAttributeMaxDynamicSharedMemorySize, SMEM_BYTES);

    sniff_idx_kernel<<<1, 32>>>((const unsigned int*)eidx);
    zero_msg_kernel<<<(N_TOTAL * 64 + 255) / 256, 256>>>();
    edge_kernel<<<E_TOTAL / TILE, NTHREADS, SMEM_BYTES>>>(
        h, eidx, eattr, ew0, eb0, ew1, eb1, ew2, eb2, ew3, eb3, edge_out);
    node_kernel<<<(N_TOTAL + TILE - 1) / TILE, NTHREADS, SMEM_BYTES>>>(
        h, nw0, nb0, nw1, nb1, nw2, nb2, nw3, nb3, h_out);
}

// round 4
// speedup vs baseline: 1.7052x; 1.7052x over previous
#include <cuda_runtime.h>
#include <cstdint>

#define E_TOTAL 800000
#define N_TOTAL 50000
#define TILE 64
#define NTHREADS 512

// Shared memory layout (in floats)
#define SA_PITCH 200   // 192 cols max, padded (multiple of 4 for float4)
#define SB_PITCH 136   // 128 cols, padded (multiple of 4)
#define OFF_SA   0
#define OFF_SB   (OFF_SA + 64*SA_PITCH)
#define OFF_SW   (OFF_SB + 64*SB_PITCH)
#define OFF_BIAS (OFF_SW + 192*128)
#define OFF_IDX  (OFF_BIAS + 128)           // 128 ints (row[64], col[64])
#define SMEM_FLOATS (OFF_IDX + 128)
#define SMEM_BYTES (SMEM_FLOATS * 4)

// scatter-add accumulator (no cudaMalloc allowed -> device global)
__device__ float g_msg[N_TOTAL * 64];
__device__ int   g_idx_is64;   // 1 if edge_index is int64, 0 if int32

__global__ void zero_msg_kernel() {
    int i = blockIdx.x * blockDim.x + threadIdx.x;
    if (i < N_TOTAL * 64) g_msg[i] = 0.0f;
}

// Sniff edge_index dtype (int32 vs int64) — see round-1 notes.
__global__ void sniff_idx_kernel(const unsigned int* __restrict__ raw) {
    if (threadIdx.x == 0) {
        int is64 = 1;
        for (int i = 0; i < 1024; i++) {
            if (raw[2 * i + 1] != 0u) { is64 = 0; break; }
        }
        g_idx_is64 = is64;
    }
}

__device__ __forceinline__ void load_wb(float* sW, const float* __restrict__ W, int nw,
                                        float* sBias, const float* __restrict__ B, int nb,
                                        int tid) {
    const float4* src = (const float4*)W;
    float4* dst = (float4*)sW;
    int n4 = nw >> 2;
    for (int i = tid; i < n4; i += NTHREADS) dst[i] = src[i];
    for (int i = tid; i < nb; i += NTHREADS) sBias[i] = B[i];
}

// One MLP layer, OUTC=128: sOut[r][c] = (relu)(sum_k sIn[r][k]*sW[k][c] + bias[c])
// 64 rows. Thread micro-tile: 4 rows (ty+16i) x 4 cols (4tx..4tx+3), fully
// vectorized: A via float4 warp-broadcast, W via float4 conflict-free.
template<int K, bool RELU>
__device__ __forceinline__ void mlp_layer128(
    const float* __restrict__ sIn, int inPitch,
    float* __restrict__ sOut, int outPitch,
    const float* __restrict__ sW, const float* __restrict__ sBias,
    int tx, int ty)
{
    float4 acc[4];
    float4 b4 = ((const float4*)sBias)[tx];
#pragma unroll
    for (int i = 0; i < 4; i++) acc[i] = b4;

#pragma unroll 2
    for (int k4 = 0; k4 < K / 4; k4++) {
        float4 a4[4];
#pragma unroll
        for (int i = 0; i < 4; i++)
            a4[i] = *(const float4*)(sIn + (ty + 16 * i) * inPitch + 4 * k4);
#pragma unroll
        for (int kk = 0; kk < 4; kk++) {
            float4 w = *(const float4*)(sW + (size_t)(4 * k4 + kk) * 128 + 4 * tx);
#pragma unroll
            for (int i = 0; i < 4; i++) {
                float a = ((const float*)&a4[i])[kk];
                acc[i].x = fmaf(a, w.x, acc[i].x);
                acc[i].y = fmaf(a, w.y, acc[i].y);
                acc[i].z = fmaf(a, w.z, acc[i].z);
                acc[i].w = fmaf(a, w.w, acc[i].w);
            }
        }
    }
#pragma unroll
    for (int i = 0; i < 4; i++) {
        float4 v = acc[i];
        if (RELU) {
            v.x = fmaxf(v.x, 0.f); v.y = fmaxf(v.y, 0.f);
            v.z = fmaxf(v.z, 0.f); v.w = fmaxf(v.w, 0.f);
        }
        *(float4*)(sOut + (ty + 16 * i) * outPitch + 4 * tx) = v;
    }
}

// Final 128->64 layer, kept in regs. Thread grid: tx2 = tid&15 (cols 4tx2..),
// ry = tid>>4 (rows ry, ry+32). acc[2] float4.
__device__ __forceinline__ void mlp_final64(
    const float* __restrict__ sIn, int inPitch,
    const float* __restrict__ sW, const float* __restrict__ sBias,
    int tx2, int ry, float4 acc[2])
{
    float4 b4 = ((const float4*)sBias)[tx2];
    acc[0] = b4; acc[1] = b4;
#pragma unroll 2
    for (int k4 = 0; k4 < 32; k4++) {
        float4 a4[2];
#pragma unroll
        for (int i = 0; i < 2; i++)
            a4[i] = *(const float4*)(sIn + (ry + 32 * i) * inPitch + 4 * k4);
#pragma unroll
        for (int kk = 0; kk < 4; kk++) {
            float4 w = *(const float4*)(sW + (size_t)(4 * k4 + kk) * 64 + 4 * tx2);
#pragma unroll
            for (int i = 0; i < 2; i++) {
                float a = ((const float*)&a4[i])[kk];
                acc[i].x = fmaf(a, w.x, acc[i].x);
                acc[i].y = fmaf(a, w.y, acc[i].y);
                acc[i].z = fmaf(a, w.z, acc[i].z);
                acc[i].w = fmaf(a, w.w, acc[i].w);
            }
        }
    }
}

__global__ void __launch_bounds__(NTHREADS, 1)
edge_kernel(const float* __restrict__ h,
            const void* __restrict__ eidx_raw,
            const float* __restrict__ eattr,
            const float* __restrict__ W0, const float* __restrict__ B0,
            const float* __restrict__ W1, const float* __restrict__ B1,
            const float* __restrict__ W2, const float* __restrict__ B2,
            const float* __restrict__ W3, const float* __restrict__ B3,
            float* __restrict__ edge_out)
{
    extern __shared__ float smem[];
    float* sA    = smem + OFF_SA;
    float* sB    = smem + OFF_SB;
    float* sW    = smem + OFF_SW;
    float* sBias = smem + OFF_BIAS;
    int*   sRow  = (int*)(smem + OFF_IDX);
    int*   sCol  = sRow + 64;

    const int tid = threadIdx.x;
    const int tx = tid & 31, ty = tid >> 5;   // ty 0..15
    const int e0 = blockIdx.x * TILE;

    if (tid < 64) {
        if (g_idx_is64) {
            const long long* e64 = (const long long*)eidx_raw;
            sRow[tid] = (int)e64[e0 + tid];
            sCol[tid] = (int)e64[E_TOTAL + e0 + tid];
        } else {
            const int* e32 = (const int*)eidx_raw;
            sRow[tid] = e32[e0 + tid];
            sCol[tid] = e32[E_TOTAL + e0 + tid];
        }
    }
    load_wb(sW, W0, 192 * 128, sBias, B0, 128, tid);
    __syncthreads();

    // Gather edge_in = [h[row] | h[col] | edge_attr], 192 floats = 48 float4/row
    for (int idx = tid; idx < 64 * 48; idx += NTHREADS) {
        int r = idx / 48, q = idx - r * 48;
        float4 v;
        if (q < 16)      v = ((const float4*)h)[(size_t)sRow[r] * 16 + q];
        else if (q < 32) v = ((const float4*)h)[(size_t)sCol[r] * 16 + (q - 16)];
        else             v = ((const float4*)eattr)[(size_t)(e0 + r) * 16 + (q - 32)];
        ((float4*)(sA + r * SA_PITCH))[q] = v;
    }
    __syncthreads();

    mlp_layer128<192, true>(sA, SA_PITCH, sB, SB_PITCH, sW, sBias, tx, ty);
    __syncthreads();
    load_wb(sW, W1, 128 * 128, sBias, B1, 128, tid);
    __syncthreads();
    mlp_layer128<128, true>(sB, SB_PITCH, sA, SA_PITCH, sW, sBias, tx, ty);
    __syncthreads();
    load_wb(sW, W2, 128 * 128, sBias, B2, 128, tid);
    __syncthreads();
    mlp_layer128<128, true>(sA, SA_PITCH, sB, SB_PITCH, sW, sBias, tx, ty);
    __syncthreads();
    load_wb(sW, W3, 128 * 64, sBias, B3, 64, tid);
    __syncthreads();

    const int tx2 = tid & 15, ry = tid >> 4;  // ry 0..31
    float4 acc[2];
    mlp_final64(sB, SB_PITCH, sW, sBias, tx2, ry, acc);

#pragma unroll
    for (int i = 0; i < 2; i++) {
        int r = ry + 32 * i;
        int col = sCol[r];
        *(float4*)(edge_out + (size_t)(e0 + r) * 64 + 4 * tx2) = acc[i];
        float* dst = &g_msg[(size_t)col * 64 + 4 * tx2];
        atomicAdd(dst + 0, acc[i].x);
        atomicAdd(dst + 1, acc[i].y);
        atomicAdd(dst + 2, acc[i].z);
        atomicAdd(dst + 3, acc[i].w);
    }
}

__global__ void __launch_bounds__(NTHREADS, 1)
node_kernel(const float* __restrict__ h,
            const float* __restrict__ W0, const float* __restrict__ B0,
            const float* __restrict__ W1, const float* __restrict__ B1,
            const float* __restrict__ W2, const float* __restrict__ B2,
            const float* __restrict__ W3, const float* __restrict__ B3,
            float* __restrict__ h_out)
{
    extern __shared__ float smem[];
    float* sA    = smem + OFF_SA;
    float* sB    = smem + OFF_SB;
    float* sW    = smem + OFF_SW;
    float* sBias = smem + OFF_BIAS;

    const int tid = threadIdx.x;
    const int tx = tid & 31, ty = tid >> 5;
    const int n0 = blockIdx.x * TILE;

    load_wb(sW, W0, 128 * 128, sBias, B0, 128, tid);

    // Gather node_in = [h[n] | msg[n]], 128 floats = 32 float4 per row
    for (int idx = tid; idx < 64 * 32; idx += NTHREADS) {
        int r = idx / 32, q = idx - r * 32;
        int n = n0 + r;
        float4 v = make_float4(0.f, 0.f, 0.f, 0.f);
        if (n < N_TOTAL) {
            if (q < 16) v = ((const float4*)h)[(size_t)n * 16 + q];
            else        v = ((const float4*)g_msg)[(size_t)n * 16 + (q - 16)];
        }
        ((float4*)(sA + r * SA_PITCH))[q] = v;
    }
    __syncthreads();

    mlp_layer128<128, true>(sA, SA_PITCH, sB, SB_PITCH, sW, sBias, tx, ty);
    __syncthreads();
    load_wb(sW, W1, 128 * 128, sBias, B1, 128, tid);
    __syncthreads();
    mlp_layer128<128, true>(sB, SB_PITCH, sA, SA_PITCH, sW, sBias, tx, ty);
    __syncthreads();
    load_wb(sW, W2, 128 * 128, sBias, B2, 128, tid);
    __syncthreads();
    mlp_layer128<128, true>(sA, SA_PITCH, sB, SB_PITCH, sW, sBias, tx, ty);
    __syncthreads();
    load_wb(sW, W3, 128 * 64, sBias, B3, 64, tid);
    __syncthreads();

    const int tx2 = tid & 15, ry = tid >> 4;
    float4 acc[2];
    mlp_final64(sB, SB_PITCH, sW, sBias, tx2, ry, acc);

#pragma unroll
    for (int i = 0; i < 2; i++) {
        int n = n0 + ry + 32 * i;
        if (n < N_TOTAL)
            *(float4*)(h_out + (size_t)n * 64 + 4 * tx2) = acc[i];
    }
}

extern "C" void kernel_launch(void* const* d_in, const int* in_sizes, int n_in,
                              void* d_out, int out_size)
{
    const float* h     = (const float*)d_in[0];
    const void*  eidx  = d_in[1];                  // int32 or int64, sniffed on device
    const float* eattr = (const float*)d_in[2];
    // dict order interleaves: ew_i, eb_i, nw_i, nb_i for i in 0..3
    const float* ew0 = (const float*)d_in[3],  *eb0 = (const float*)d_in[4];
    const float* nw0 = (const float*)d_in[5],  *nb0 = (const float*)d_in[6];
    const float* ew1 = (const float*)d_in[7],  *eb1 = (const float*)d_in[8];
    const float* nw1 = (const float*)d_in[9],  *nb1 = (const float*)d_in[10];
    const float* ew2 = (const float*)d_in[11], *eb2 = (const float*)d_in[12];
    const float* nw2 = (const float*)d_in[13], *nb2 = (const float*)d_in[14];
    const float* ew3 = (const float*)d_in[15], *eb3 = (const float*)d_in[16];
    const float* nw3 = (const float*)d_in[17], *nb3 = (const float*)d_in[18];

    float* out      = (float*)d_out;
    float* h_out    = out;                        // [50000, 64]
    float* edge_out = out + (size_t)N_TOTAL * 64; // [800000, 64]

    cudaFuncSetAttribute(edge_kernel, cudaFuncAttributeMaxDynamicSharedMemorySize, SMEM_BYTES);
    cudaFuncSetAttribute(node_kernel, cudaFuncAttributeMaxDynamicSharedMemorySize, SMEM_BYTES);

    sniff_idx_kernel<<<1, 32>>>((const unsigned int*)eidx);
    zero_msg_kernel<<<(N_TOTAL * 64 + 255) / 256, 256>>>();
    edge_kernel<<<E_TOTAL / TILE, NTHREADS, SMEM_BYTES>>>(
        h, eidx, eattr, ew0, eb0, ew1, eb1, ew2, eb2, ew3, eb3, edge_out);
    node_kernel<<<(N_TOTAL + TILE - 1) / TILE, NTHREADS, SMEM_BYTES>>>(
        h, nw0, nb0, nw1, nb1, nw2, nb2, nw3, nb3, h_out);
}

// round 6
// speedup vs baseline: 3.5573x; 2.0861x over previous
#include <cuda_runtime.h>
#include <cuda_bf16.h>
#include <cstdint>

#define E_TOTAL 800000
#define N_TOTAL 50000
#define MTILE 128
#define NTHREADS 256

// ---------------- SMEM byte layout ----------------
// A planes: 128 rows x 400B pitch (192 bf16 max + 16B pad -> conflict-free)
#define OFF_AHI  0
#define OFF_ALO  51200
#define OFF_W    102400    // hi plane then lo plane, flat copy (max 2*51200)
#define OFF_BIAS 204800    // 4 layers x 128 floats
#define OFF_IDX  206848    // row[128], col[128] ints
#define SMEM_BYTES 207872

// ---------------- device globals (no cudaMalloc allowed) ----------------
__device__ float g_msg[N_TOTAL * 64];
__device__ int   g_idx_is64;
// pre-split bf16 weight images, transposed to [N][K+8] row-major, hi plane then lo plane
__device__ __align__(16) unsigned char g_eW[276480]; // L0@0(102400) L1@102400(69632) L2@172032(69632) L3@241664(34816)
__device__ __align__(16) unsigned char g_nW[243712]; // L0@0 L1@69632 L2@139264 L3@208896

// ---------------- helpers ----------------
__device__ __forceinline__ uint32_t smem_u32(const void* p) {
    uint32_t a;
    asm("{ .reg .u64 t; cvta.to.shared.u64 t, %1; cvt.u32.u64 %0, t; }" : "=r"(a) : "l"(p));
    return a;
}
#define LDMX4(r, a)                                                              \
    asm volatile("ldmatrix.sync.aligned.m8n8.x4.shared.b16 {%0,%1,%2,%3}, [%4];" \
        : "=r"((r)[0]), "=r"((r)[1]), "=r"((r)[2]), "=r"((r)[3]) : "r"(a))
#define LDMX2(b0, b1, a)                                                         \
    asm volatile("ldmatrix.sync.aligned.m8n8.x2.shared.b16 {%0,%1}, [%2];"       \
        : "=r"(b0), "=r"(b1) : "r"(a))

__device__ __forceinline__ void mma_bf16(float* c, uint32_t a0, uint32_t a1,
                                         uint32_t a2, uint32_t a3,
                                         uint32_t b0, uint32_t b1) {
    asm volatile(
        "mma.sync.aligned.m16n8k16.row.col.f32.bf16.bf16.f32 "
        "{%0,%1,%2,%3}, {%4,%5,%6,%7}, {%8,%9}, {%0,%1,%2,%3};"
        : "+f"(c[0]), "+f"(c[1]), "+f"(c[2]), "+f"(c[3])
        : "r"(a0), "r"(a1), "r"(a2), "r"(a3), "r"(b0), "r"(b1));
}

__device__ __forceinline__ void split2(float f0, float f1, uint32_t& hi, uint32_t& lo) {
    __nv_bfloat162 h = __floats2bfloat162_rn(f0, f1);  // low half = f0
    float r0 = f0 - __bfloat162float(h.x);
    float r1 = f1 - __bfloat162float(h.y);
    __nv_bfloat162 l = __floats2bfloat162_rn(r0, r1);
    hi = *reinterpret_cast<uint32_t*>(&h);
    lo = *reinterpret_cast<uint32_t*>(&l);
}

__device__ __forceinline__ void copy16(unsigned char* dst, const unsigned char* src,
                                       int bytes, int t, int nt) {
    const int4* s = (const int4*)src;
    int4* d = (int4*)dst;
    int n = bytes >> 4;
    for (int i = t; i < n; i += nt) d[i] = s[i];
}

// ---------------- small kernels ----------------
__global__ void zero_msg_kernel() {
    int i = blockIdx.x * blockDim.x + threadIdx.x;
    if (i < N_TOTAL * 64) g_msg[i] = 0.0f;
}
__global__ void sniff_idx_kernel(const unsigned int* __restrict__ raw) {
    if (threadIdx.x == 0) {
        int is64 = 1;
        for (int i = 0; i < 1024; i++)
            if (raw[2 * i + 1] != 0u) { is64 = 0; break; }
        g_idx_is64 = is64;
    }
}
// fp32 W[K][N] -> bf16 hi/lo planes, transposed [N][K+8]
__global__ void convert_w_kernel(const float* __restrict__ W, int isNode,
                                 int off, int N, int K) {
    unsigned char* base = (isNode ? g_nW : g_eW) + off;
    int PW = K + 8;
    int planeB = N * PW * 2;
    int total = N * K;
    for (int i = blockIdx.x * blockDim.x + threadIdx.x; i < total;
         i += gridDim.x * blockDim.x) {
        int n = i % N, k = i / N;
        float w = W[(size_t)k * N + n];
        __nv_bfloat16 hb = __float2bfloat16(w);
        float rem = w - __bfloat162float(hb);
        __nv_bfloat16 lb = __float2bfloat16(rem);
        *(__nv_bfloat16*)(base + n * PW * 2 + k * 2) = hb;
        *(__nv_bfloat16*)(base + planeB + n * PW * 2 + k * 2) = lb;
    }
}

// ---------------- GEMM: acc += (Ahi+Alo) x Whi + Ahi x Wlo ----------------
// Warp grid 4(m) x 2(n): warp owns 32 rows x N/2 cols.
template<int K, int N>
__device__ __forceinline__ void gemm3(uint32_t sb, int planeB, int wid, int lane,
                                      float acc[][2][4]) {
    constexpr int PWB = (K + 8) * 2;
    constexpr int NBW = N / 16;
    const int mrow = (wid & 3) * 32;
    const int ncol = (wid >> 2) * (N / 2);

#pragma unroll
    for (int nb = 0; nb < NBW; nb++)
#pragma unroll
        for (int mt = 0; mt < 2; mt++)
#pragma unroll
            for (int i = 0; i < 4; i++) acc[nb][mt][i] = 0.0f;

    const uint32_t aRowOff = (uint32_t)(mrow + (lane & 15)) * 400 + ((lane >> 4) << 4);
    const uint32_t bRowOff = (uint32_t)(ncol + (lane & 7)) * PWB + (((lane >> 3) & 1) << 4);

#pragma unroll
    for (int half = 0; half < 2; half++) {
        uint32_t Wb = sb + OFF_W + half * planeB + bRowOff;
#pragma unroll 2
        for (int kc = 0; kc < K / 16; kc++) {
            uint32_t acol = kc * 32;
            uint32_t ah[8];
            LDMX4(ah,     sb + OFF_AHI + aRowOff + acol);
            LDMX4(ah + 4, sb + OFF_AHI + aRowOff + acol + 6400);
            uint32_t al[8];
            if (half == 0) {
                LDMX4(al,     sb + OFF_ALO + aRowOff + acol);
                LDMX4(al + 4, sb + OFF_ALO + aRowOff + acol + 6400);
            }
#pragma unroll
            for (int nb = 0; nb < NBW; nb++) {
                uint32_t b0, b1;
                LDMX2(b0, b1, Wb + (uint32_t)nb * 8 * PWB + kc * 32);
                mma_bf16(acc[nb][0], ah[0], ah[1], ah[2], ah[3], b0, b1);
                mma_bf16(acc[nb][1], ah[4], ah[5], ah[6], ah[7], b0, b1);
                if (half == 0) {
                    mma_bf16(acc[nb][0], al[0], al[1], al[2], al[3], b0, b1);
                    mma_bf16(acc[nb][1], al[4], al[5], al[6], al[7], b0, b1);
                }
            }
        }
    }
}

// mid-layer epilogue: bias + relu + split -> next A hi/lo planes
template<int N>
__device__ __forceinline__ void epi_mid(float acc[][2][4], unsigned char* sm,
                                        const float* bias, int wid, int lane) {
    constexpr int NBW = N / 16;
    const int mrow = (wid & 3) * 32;
    const int ncol = (wid >> 2) * (N / 2);
    const int g = lane >> 2, tig = lane & 3;
#pragma unroll
    for (int nb = 0; nb < NBW; nb++) {
        int col = ncol + nb * 8 + 2 * tig;
        float bb0 = bias[col], bb1 = bias[col + 1];
#pragma unroll
        for (int mt = 0; mt < 2; mt++) {
            int r0 = mrow + mt * 16 + g;
            uint32_t hi, lo;
            float f0 = fmaxf(acc[nb][mt][0] + bb0, 0.0f);
            float f1 = fmaxf(acc[nb][mt][1] + bb1, 0.0f);
            split2(f0, f1, hi, lo);
            *(uint32_t*)(sm + OFF_AHI + r0 * 400 + col * 2) = hi;
            *(uint32_t*)(sm + OFF_ALO + r0 * 400 + col * 2) = lo;
            f0 = fmaxf(acc[nb][mt][2] + bb0, 0.0f);
            f1 = fmaxf(acc[nb][mt][3] + bb1, 0.0f);
            split2(f0, f1, hi, lo);
            *(uint32_t*)(sm + OFF_AHI + (r0 + 8) * 400 + col * 2) = hi;
            *(uint32_t*)(sm + OFF_ALO + (r0 + 8) * 400 + col * 2) = lo;
        }
    }
}

// ---------------- edge kernel ----------------
__global__ void __launch_bounds__(NTHREADS, 1)
edge_kernel(const float* __restrict__ h, const void* __restrict__ eidx_raw,
            const float* __restrict__ eattr,
            const float* __restrict__ B0, const float* __restrict__ B1,
            const float* __restrict__ B2, const float* __restrict__ B3,
            float* __restrict__ edge_out)
{
    extern __shared__ unsigned char sm[];
    uint32_t sb = smem_u32(sm);
    const int tid = threadIdx.x, wid = tid >> 5, lane = tid & 31;
    const int e0 = blockIdx.x * MTILE;
    float* sBias = (float*)(sm + OFF_BIAS);
    int* sRow = (int*)(sm + OFF_IDX);
    int* sCol = sRow + 128;

    if (tid < 128) {
        sBias[tid] = B0[tid]; sBias[128 + tid] = B1[tid]; sBias[256 + tid] = B2[tid];
        if (tid < 64) sBias[384 + tid] = B3[tid];
        if (g_idx_is64) {
            const long long* e64 = (const long long*)eidx_raw;
            sRow[tid] = (int)e64[e0 + tid];
            sCol[tid] = (int)e64[E_TOTAL + e0 + tid];
        } else {
            const int* e32 = (const int*)eidx_raw;
            sRow[tid] = e32[e0 + tid];
            sCol[tid] = e32[E_TOTAL + e0 + tid];
        }
    }
    __syncthreads();

    // gather (tid<128) overlapped with W0 staging (tid>=128)
    if (tid < 128) {
        int row = tid;
        int hr = sRow[row], hc = sCol[row];
        unsigned char* Ah = sm + OFF_AHI + row * 400;
        unsigned char* Al = sm + OFF_ALO + row * 400;
#pragma unroll
        for (int c = 0; c < 6; c++) {
            const float4* p = (c < 2) ? (const float4*)(h + (size_t)hr * 64 + 32 * c)
                            : (c < 4) ? (const float4*)(h + (size_t)hc * 64 + 32 * (c - 2))
                                      : (const float4*)(eattr + (size_t)(e0 + row) * 64 + 32 * (c - 4));
#pragma unroll
            for (int j = 0; j < 8; j++) {
                float4 v = p[j];
                uint32_t h0, l0, h1, l1;
                split2(v.x, v.y, h0, l0);
                split2(v.z, v.w, h1, l1);
                int ob = c * 64 + j * 8;
                *(uint32_t*)(Ah + ob)     = h0;
                *(uint32_t*)(Ah + ob + 4) = h1;
                *(uint32_t*)(Al + ob)     = l0;
                *(uint32_t*)(Al + ob + 4) = l1;
            }
        }
    } else {
        copy16(sm + OFF_W, g_eW, 102400, tid - 128, 128);
    }
    __syncthreads();

    float acc[8][2][4];

    gemm3<192, 128>(sb, 51200, wid, lane, acc);
    __syncthreads();
    epi_mid<128>(acc, sm, sBias, wid, lane);
    __syncthreads();
    copy16(sm + OFF_W, g_eW + 102400, 69632, tid, NTHREADS);
    __syncthreads();

    gemm3<128, 128>(sb, 34816, wid, lane, acc);
    __syncthreads();
    epi_mid<128>(acc, sm, sBias + 128, wid, lane);
    __syncthreads();
    copy16(sm + OFF_W, g_eW + 172032, 69632, tid, NTHREADS);
    __syncthreads();

    gemm3<128, 128>(sb, 34816, wid, lane, acc);
    __syncthreads();
    epi_mid<128>(acc, sm, sBias + 256, wid, lane);
    __syncthreads();
    copy16(sm + OFF_W, g_eW + 241664, 34816, tid, NTHREADS);
    __syncthreads();

    gemm3<128, 64>(sb, 17408, wid, lane, acc);
    __syncthreads();
    // final: bias, stage fp32 out tile in SMEM (reuse A_hi region, pitch 272B)
    {
        const int mrow = (wid & 3) * 32, ncol = (wid >> 2) * 32;
        const int g = lane >> 2, tig = lane & 3;
        const float* bias = sBias + 384;
#pragma unroll
        for (int nb = 0; nb < 4; nb++) {
            int col = ncol + nb * 8 + 2 * tig;
            float bb0 = bias[col], bb1 = bias[col + 1];
#pragma unroll
            for (int mt = 0; mt < 2; mt++) {
                int r0 = mrow + mt * 16 + g;
                float2 v0 = make_float2(acc[nb][mt][0] + bb0, acc[nb][mt][1] + bb1);
                float2 v1 = make_float2(acc[nb][mt][2] + bb0, acc[nb][mt][3] + bb1);
                *(float2*)(sm + OFF_AHI + r0 * 272 + col * 4) = v0;
                *(float2*)(sm + OFF_AHI + (r0 + 8) * 272 + col * 4) = v1;
            }
        }
    }
    __syncthreads();
    // scatter: edge_out write (coalesced per-row) + atomic msg accumulate
    if (tid < 128) {
        const float* so = (const float*)(sm + OFF_AHI + tid * 272);
        float* eo = edge_out + (size_t)(e0 + tid) * 64;
#pragma unroll
        for (int q = 0; q < 16; q++) ((float4*)eo)[q] = ((const float4*)so)[q];
        float* md = g_msg + (size_t)sCol[tid] * 64;
#pragma unroll
        for (int j = 0; j < 64; j++) atomicAdd(md + j, so[j]);
    }
}

// ---------------- node kernel ----------------
__global__ void __launch_bounds__(NTHREADS, 1)
node_kernel(const float* __restrict__ h,
            const float* __restrict__ B0, const float* __restrict__ B1,
            const float* __restrict__ B2, const float* __restrict__ B3,
            float* __restrict__ h_out)
{
    extern __shared__ unsigned char sm[];
    uint32_t sb = smem_u32(sm);
    const int tid = threadIdx.x, wid = tid >> 5, lane = tid & 31;
    const int n0 = blockIdx.x * MTILE;
    float* sBias = (float*)(sm + OFF_BIAS);

    if (tid < 128) {
        sBias[tid] = B0[tid]; sBias[128 + tid] = B1[tid]; sBias[256 + tid] = B2[tid];
        if (tid < 64) sBias[384 + tid] = B3[tid];
    }
    // gather (tid<128) overlapped with W0 staging (tid>=128)
    if (tid < 128) {
        int row = tid;
        int n = n0 + row;
        bool ok = (n < N_TOTAL);
        unsigned char* Ah = sm + OFF_AHI + row * 400;
        unsigned char* Al = sm + OFF_ALO + row * 400;
#pragma unroll
        for (int c = 0; c < 4; c++) {
            float4 v[8];
            if (ok) {
                const float4* p = (c < 2) ? (const float4*)(h + (size_t)n * 64 + 32 * c)
                                          : (const float4*)(g_msg + (size_t)n * 64 + 32 * (c - 2));
#pragma unroll
                for (int j = 0; j < 8; j++) v[j] = p[j];
            } else {
#pragma unroll
                for (int j = 0; j < 8; j++) v[j] = make_float4(0.f, 0.f, 0.f, 0.f);
            }
#pragma unroll
            for (int j = 0; j < 8; j++) {
                uint32_t h0, l0, h1, l1;
                split2(v[j].x, v[j].y, h0, l0);
                split2(v[j].z, v[j].w, h1, l1);
                int ob = c * 64 + j * 8;
                *(uint32_t*)(Ah + ob)     = h0;
                *(uint32_t*)(Ah + ob + 4) = h1;
                *(uint32_t*)(Al + ob)     = l0;
                *(uint32_t*)(Al + ob + 4) = l1;
            }
        }
    } else {
        copy16(sm + OFF_W, g_nW, 69632, tid - 128, 128);
    }
    __syncthreads();

    float acc[8][2][4];

    gemm3<128, 128>(sb, 34816, wid, lane, acc);
    __syncthreads();
    epi_mid<128>(acc, sm, sBias, wid, lane);
    __syncthreads();
    copy16(sm + OFF_W, g_nW + 69632, 69632, tid, NTHREADS);
    __syncthreads();

    gemm3<128, 128>(sb, 34816, wid, lane, acc);
    __syncthreads();
    epi_mid<128>(acc, sm, sBias + 128, wid, lane);
    __syncthreads();
    copy16(sm + OFF_W, g_nW + 139264, 69632, tid, NTHREADS);
    __syncthreads();

    gemm3<128, 128>(sb, 34816, wid, lane, acc);
    __syncthreads();
    epi_mid<128>(acc, sm, sBias + 256, wid, lane);
    __syncthreads();
    copy16(sm + OFF_W, g_nW + 208896, 34816, tid, NTHREADS);
    __syncthreads();

    gemm3<128, 64>(sb, 17408, wid, lane, acc);
    // final: write h_out directly from regs
    {
        const int mrow = (wid & 3) * 32, ncol = (wid >> 2) * 32;
        const int g = lane >> 2, tig = lane & 3;
        const float* bias = sBias + 384;
#pragma unroll
        for (int nb = 0; nb < 4; nb++) {
            int col = ncol + nb * 8 + 2 * tig;
            float bb0 = bias[col], bb1 = bias[col + 1];
#pragma unroll
            for (int mt = 0; mt < 2; mt++) {
                int r = n0 + mrow + mt * 16 + g;
                if (r < N_TOTAL)
                    *(float2*)(h_out + (size_t)r * 64 + col) =
                        make_float2(acc[nb][mt][0] + bb0, acc[nb][mt][1] + bb1);
                int r2 = r + 8;
                if (r2 < N_TOTAL)
                    *(float2*)(h_out + (size_t)r2 * 64 + col) =
                        make_float2(acc[nb][mt][2] + bb0, acc[nb][mt][3] + bb1);
            }
        }
    }
}

// ---------------- host ----------------
extern "C" void kernel_launch(void* const* d_in, const int* in_sizes, int n_in,
                              void* d_out, int out_size)
{
    const float* h     = (const float*)d_in[0];
    const void*  eidx  = d_in[1];
    const float* eattr = (const float*)d_in[2];
    const float* ew0 = (const float*)d_in[3],  *eb0 = (const float*)d_in[4];
    const float* nw0 = (const float*)d_in[5],  *nb0 = (const float*)d_in[6];
    const float* ew1 = (const float*)d_in[7],  *eb1 = (const float*)d_in[8];
    const float* nw1 = (const float*)d_in[9],  *nb1 = (const float*)d_in[10];
    const float* ew2 = (const float*)d_in[11], *eb2 = (const float*)d_in[12];
    const float* nw2 = (const float*)d_in[13], *nb2 = (const float*)d_in[14];
    const float* ew3 = (const float*)d_in[15], *eb3 = (const float*)d_in[16];
    const float* nw3 = (const float*)d_in[17], *nb3 = (const float*)d_in[18];

    float* out      = (float*)d_out;
    float* h_out    = out;                        // [50000, 64]
    float* edge_out = out + (size_t)N_TOTAL * 64; // [800000, 64]

    cudaFuncSetAttribute(edge_kernel, cudaFuncAttributeMaxDynamicSharedMemorySize, SMEM_BYTES);
    cudaFuncSetAttribute(node_kernel, cudaFuncAttributeMaxDynamicSharedMemorySize, SMEM_BYTES);

    sniff_idx_kernel<<<1, 32>>>((const unsigned int*)eidx);
    zero_msg_kernel<<<(N_TOTAL * 64 + 255) / 256, 256>>>();

    // weight images: (W, isNode, off, N, K)
    convert_w_kernel<<<48, 256>>>(ew0, 0, 0,      128, 192);
    convert_w_kernel<<<48, 256>>>(ew1, 0, 102400, 128, 128);
    convert_w_kernel<<<48, 256>>>(ew2, 0, 172032, 128, 128);
    convert_w_kernel<<<48, 256>>>(ew3, 0, 241664,  64, 128);
    convert_w_kernel<<<48, 256>>>(nw0, 1, 0,      128, 128);
    convert_w_kernel<<<48, 256>>>(nw1, 1, 69632,  128, 128);
    convert_w_kernel<<<48, 256>>>(nw2, 1, 139264, 128, 128);
    convert_w_kernel<<<48, 256>>>(nw3, 1, 208896,  64, 128);

    edge_kernel<<<E_TOTAL / MTILE, NTHREADS, SMEM_BYTES>>>(
        h, eidx, eattr, eb0, eb1, eb2, eb3, edge_out);
    node_kernel<<<(N_TOTAL + MTILE - 1) / MTILE, NTHREADS, SMEM_BYTES>>>(
        h, nb0, nb1, nb2, nb3, h_out);
}

// round 7
// speedup vs baseline: 4.3855x; 1.2328x over previous
#include <cuda_runtime.h>
#include <cuda_bf16.h>
#include <cstdint>

#define E_TOTAL 800000
#define N_TOTAL 50000
#define MTILE 128
#define NTHREADS 256

// ---------------- SMEM byte layout ----------------
#define OFF_AHI  0
#define OFF_ALO  51200
#define OFF_W    102400    // hi plane then lo plane
#define OFF_BIAS 204800
#define OFF_IDX  206848
#define SMEM_BYTES 207872

// ---------------- device globals ----------------
__device__ float g_msg[N_TOTAL * 64];
__device__ int   g_idx_is64;
// bf16 hi/lo weight planes, transposed [N][K+8]
__device__ __align__(16) unsigned char g_eW[276480]; // L0@0 L1@102400 L2@172032 L3@241664
__device__ __align__(16) unsigned char g_nW[243712]; // L0@0 L1@69632 L2@139264 L3@208896

// ---------------- helpers ----------------
__device__ __forceinline__ uint32_t smem_u32(const void* p) {
    uint32_t a;
    asm("{ .reg .u64 t; cvta.to.shared.u64 t, %1; cvt.u32.u64 %0, t; }" : "=r"(a) : "l"(p));
    return a;
}
#define LDMX4(r, a)                                                              \
    asm volatile("ldmatrix.sync.aligned.m8n8.x4.shared.b16 {%0,%1,%2,%3}, [%4];" \
        : "=r"((r)[0]), "=r"((r)[1]), "=r"((r)[2]), "=r"((r)[3]) : "r"(a))
#define LDMX2(b0, b1, a)                                                         \
    asm volatile("ldmatrix.sync.aligned.m8n8.x2.shared.b16 {%0,%1}, [%2];"       \
        : "=r"(b0), "=r"(b1) : "r"(a))
#define CP_ASYNC16(sa, g)                                                        \
    asm volatile("cp.async.cg.shared.global [%0], [%1], 16;" :: "r"(sa), "l"(g))
#define CP_COMMIT() asm volatile("cp.async.commit_group;" ::: "memory")
#define CP_WAIT()   asm volatile("cp.async.wait_group 0;" ::: "memory")

__device__ __forceinline__ void mma_bf16(float* c, uint32_t a0, uint32_t a1,
                                         uint32_t a2, uint32_t a3,
                                         uint32_t b0, uint32_t b1) {
    asm volatile(
        "mma.sync.aligned.m16n8k16.row.col.f32.bf16.bf16.f32 "
        "{%0,%1,%2,%3}, {%4,%5,%6,%7}, {%8,%9}, {%0,%1,%2,%3};"
        : "+f"(c[0]), "+f"(c[1]), "+f"(c[2]), "+f"(c[3])
        : "r"(a0), "r"(a1), "r"(a2), "r"(a3), "r"(b0), "r"(b1));
}

__device__ __forceinline__ void split2(float f0, float f1, uint32_t& hi, uint32_t& lo) {
    __nv_bfloat162 h = __floats2bfloat162_rn(f0, f1);
    float r0 = f0 - __bfloat162float(h.x);
    float r1 = f1 - __bfloat162float(h.y);
    __nv_bfloat162 l = __floats2bfloat162_rn(r0, r1);
    hi = *reinterpret_cast<uint32_t*>(&h);
    lo = *reinterpret_cast<uint32_t*>(&l);
}

__device__ __forceinline__ void copy16(unsigned char* dst, const unsigned char* src,
                                       int bytes, int t, int nt) {
    const int4* s = (const int4*)src;
    int4* d = (int4*)dst;
    int n = bytes >> 4;
    for (int i = t; i < n; i += nt) d[i] = s[i];
}
__device__ __forceinline__ void cp_async_copy(unsigned char* dstS, const unsigned char* src,
                                              int bytes, int t, int nt) {
    uint32_t d = smem_u32(dstS);
    for (int i = t * 16; i < bytes; i += nt * 16)
        CP_ASYNC16(d + (uint32_t)i, src + i);
}

// ---------------- fused prologue ----------------
__device__ __forceinline__ void convert_one(const float* __restrict__ W,
                                            unsigned char* base, int N, int K,
                                            int g, int NT) {
    int PW = K + 8;
    int planeB = N * PW * 2;
    int total = N * K;
    for (int i = g; i < total; i += NT) {
        int n = i % N, k = i / N;
        float w = W[(size_t)k * N + n];
        __nv_bfloat16 hb = __float2bfloat16(w);
        float rem = w - __bfloat162float(hb);
        __nv_bfloat16 lb = __float2bfloat16(rem);
        *(__nv_bfloat16*)(base + n * PW * 2 + k * 2) = hb;
        *(__nv_bfloat16*)(base + planeB + n * PW * 2 + k * 2) = lb;
    }
}

__global__ void prologue_kernel(const unsigned int* __restrict__ raw,
                                const float* __restrict__ ew0, const float* __restrict__ ew1,
                                const float* __restrict__ ew2, const float* __restrict__ ew3,
                                const float* __restrict__ nw0, const float* __restrict__ nw1,
                                const float* __restrict__ nw2, const float* __restrict__ nw3)
{
    const int tid = threadIdx.x;
    const int g = blockIdx.x * blockDim.x + tid;
    const int NT = gridDim.x * blockDim.x;

    // parallel dtype sniff (block 0)
    if (blockIdx.x == 0) {
        __shared__ int s_ok;
        if (tid == 0) s_ok = 1;
        __syncthreads();
        int bad = 0;
#pragma unroll
        for (int j = 0; j < 4; j++)
            if (raw[2 * (tid * 4 + j) + 1] != 0u) bad = 1;
        if (bad) s_ok = 0;
        __syncthreads();
        if (tid == 0) g_idx_is64 = s_ok;
    }

    // zero message accumulator
    float4* m4 = (float4*)g_msg;
    float4 z = make_float4(0.f, 0.f, 0.f, 0.f);
    for (int i = g; i < N_TOTAL * 16; i += NT) m4[i] = z;

    // weight conversions
    convert_one(ew0, g_eW + 0,      128, 192, g, NT);
    convert_one(ew1, g_eW + 102400, 128, 128, g, NT);
    convert_one(ew2, g_eW + 172032, 128, 128, g, NT);
    convert_one(ew3, g_eW + 241664,  64, 128, g, NT);
    convert_one(nw0, g_nW + 0,      128, 128, g, NT);
    convert_one(nw1, g_nW + 69632,  128, 128, g, NT);
    convert_one(nw2, g_nW + 139264, 128, 128, g, NT);
    convert_one(nw3, g_nW + 208896,  64, 128, g, NT);
}

// ---------------- GEMM: acc = Ahi*Whi + Alo*Whi + Ahi*Wlo ----------------
// Warp grid 4(m) x 2(n). Single kc loop: A frags shared across both W planes.
template<int K, int N>
__device__ __forceinline__ void gemm3(uint32_t sb, int planeB, int wid, int lane,
                                      float acc[][2][4]) {
    constexpr int PWB = (K + 8) * 2;
    constexpr int NBW = N / 16;
    const int mrow = (wid & 3) * 32;
    const int ncol = (wid >> 2) * (N / 2);

#pragma unroll
    for (int nb = 0; nb < NBW; nb++)
#pragma unroll
        for (int mt = 0; mt < 2; mt++)
#pragma unroll
            for (int i = 0; i < 4; i++) acc[nb][mt][i] = 0.0f;

    const uint32_t aRowOff = (uint32_t)(mrow + (lane & 15)) * 400 + ((lane >> 4) << 4);
    const uint32_t bRowOff = (uint32_t)(ncol + (lane & 7)) * PWB + (((lane >> 3) & 1) << 4);
    const uint32_t WbH = sb + OFF_W + bRowOff;
    const uint32_t WbL = WbH + (uint32_t)planeB;

#pragma unroll 2
    for (int kc = 0; kc < K / 16; kc++) {
        uint32_t acol = kc * 32;
        uint32_t ah[8], al[8];
        LDMX4(ah,     sb + OFF_AHI + aRowOff + acol);
        LDMX4(ah + 4, sb + OFF_AHI + aRowOff + acol + 6400);
        LDMX4(al,     sb + OFF_ALO + aRowOff + acol);
        LDMX4(al + 4, sb + OFF_ALO + aRowOff + acol + 6400);
#pragma unroll
        for (int nb = 0; nb < NBW; nb++) {
            uint32_t boff = (uint32_t)nb * 8 * PWB + kc * 32;
            uint32_t bh0, bh1, bl0, bl1;
            LDMX2(bh0, bh1, WbH + boff);
            LDMX2(bl0, bl1, WbL + boff);
            mma_bf16(acc[nb][0], ah[0], ah[1], ah[2], ah[3], bh0, bh1);
            mma_bf16(acc[nb][1], ah[4], ah[5], ah[6], ah[7], bh0, bh1);
            mma_bf16(acc[nb][0], al[0], al[1], al[2], al[3], bh0, bh1);
            mma_bf16(acc[nb][1], al[4], al[5], al[6], al[7], bh0, bh1);
            mma_bf16(acc[nb][0], ah[0], ah[1], ah[2], ah[3], bl0, bl1);
            mma_bf16(acc[nb][1], ah[4], ah[5], ah[6], ah[7], bl0, bl1);
        }
    }
}

// mid-layer epilogue: bias + relu + split -> next A hi/lo planes
template<int N>
__device__ __forceinline__ void epi_mid(float acc[][2][4], unsigned char* sm,
                                        const float* bias, int wid, int lane) {
    constexpr int NBW = N / 16;
    const int mrow = (wid & 3) * 32;
    const int ncol = (wid >> 2) * (N / 2);
    const int gq = lane >> 2, tig = lane & 3;
#pragma unroll
    for (int nb = 0; nb < NBW; nb++) {
        int col = ncol + nb * 8 + 2 * tig;
        float bb0 = bias[col], bb1 = bias[col + 1];
#pragma unroll
        for (int mt = 0; mt < 2; mt++) {
            int r0 = mrow + mt * 16 + gq;
            uint32_t hi, lo;
            float f0 = fmaxf(acc[nb][mt][0] + bb0, 0.0f);
            float f1 = fmaxf(acc[nb][mt][1] + bb1, 0.0f);
            split2(f0, f1, hi, lo);
            *(uint32_t*)(sm + OFF_AHI + r0 * 400 + col * 2) = hi;
            *(uint32_t*)(sm + OFF_ALO + r0 * 400 + col * 2) = lo;
            f0 = fmaxf(acc[nb][mt][2] + bb0, 0.0f);
            f1 = fmaxf(acc[nb][mt][3] + bb1, 0.0f);
            split2(f0, f1, hi, lo);
            *(uint32_t*)(sm + OFF_AHI + (r0 + 8) * 400 + col * 2) = hi;
            *(uint32_t*)(sm + OFF_ALO + (r0 + 8) * 400 + col * 2) = lo;
        }
    }
}

// ---------------- edge kernel ----------------
__global__ void __launch_bounds__(NTHREADS, 1)
edge_kernel(const float* __restrict__ h, const void* __restrict__ eidx_raw,
            const float* __restrict__ eattr,
            const float* __restrict__ B0, const float* __restrict__ B1,
            const float* __restrict__ B2, const float* __restrict__ B3,
            float* __restrict__ edge_out, int blkoff)
{
    extern __shared__ unsigned char sm[];
    uint32_t sb = smem_u32(sm);
    const int tid = threadIdx.x, wid = tid >> 5, lane = tid & 31;
    const int e0 = (blockIdx.x + blkoff) * MTILE;
    float* sBias = (float*)(sm + OFF_BIAS);
    int* sRow = (int*)(sm + OFF_IDX);
    int* sCol = sRow + 128;

    if (tid < 128) {
        sBias[tid] = B0[tid]; sBias[128 + tid] = B1[tid]; sBias[256 + tid] = B2[tid];
        if (tid < 64) sBias[384 + tid] = B3[tid];
        if (g_idx_is64) {
            const long long* e64 = (const long long*)eidx_raw;
            sRow[tid] = (int)e64[e0 + tid];
            sCol[tid] = (int)e64[E_TOTAL + e0 + tid];
        } else {
            const int* e32 = (const int*)eidx_raw;
            sRow[tid] = e32[e0 + tid];
            sCol[tid] = e32[E_TOTAL + e0 + tid];
        }
    }
    __syncthreads();

    if (tid < 128) {
        int row = tid;
        int hr = sRow[row], hc = sCol[row];
        unsigned char* Ah = sm + OFF_AHI + row * 400;
        unsigned char* Al = sm + OFF_ALO + row * 400;
#pragma unroll
        for (int c = 0; c < 6; c++) {
            const float4* p = (c < 2) ? (const float4*)(h + (size_t)hr * 64 + 32 * c)
                            : (c < 4) ? (const float4*)(h + (size_t)hc * 64 + 32 * (c - 2))
                                      : (const float4*)(eattr + (size_t)(e0 + row) * 64 + 32 * (c - 4));
#pragma unroll
            for (int j = 0; j < 8; j++) {
                float4 v = p[j];
                uint32_t h0, l0, h1, l1;
                split2(v.x, v.y, h0, l0);
                split2(v.z, v.w, h1, l1);
                int ob = c * 64 + j * 8;
                *(uint32_t*)(Ah + ob)     = h0;
                *(uint32_t*)(Ah + ob + 4) = h1;
                *(uint32_t*)(Al + ob)     = l0;
                *(uint32_t*)(Al + ob + 4) = l1;
            }
        }
    } else {
        copy16(sm + OFF_W, g_eW, 102400, tid - 128, 128);
    }
    __syncthreads();

    float acc[8][2][4];

    gemm3<192, 128>(sb, 51200, wid, lane, acc);
    __syncthreads();
    cp_async_copy(sm + OFF_W, g_eW + 102400, 69632, tid, NTHREADS); CP_COMMIT();
    epi_mid<128>(acc, sm, sBias, wid, lane);
    CP_WAIT();
    __syncthreads();

    gemm3<128, 128>(sb, 34816, wid, lane, acc);
    __syncthreads();
    cp_async_copy(sm + OFF_W, g_eW + 172032, 69632, tid, NTHREADS); CP_COMMIT();
    epi_mid<128>(acc, sm, sBias + 128, wid, lane);
    CP_WAIT();
    __syncthreads();

    gemm3<128, 128>(sb, 34816, wid, lane, acc);
    __syncthreads();
    cp_async_copy(sm + OFF_W, g_eW + 241664, 34816, tid, NTHREADS); CP_COMMIT();
    epi_mid<128>(acc, sm, sBias + 256, wid, lane);
    CP_WAIT();
    __syncthreads();

    gemm3<128, 64>(sb, 17408, wid, lane, acc);
    __syncthreads();
    // final: bias, stage fp32 out tile (pitch 272B) in A region
    {
        const int mrow = (wid & 3) * 32, ncol = (wid >> 2) * 32;
        const int gq = lane >> 2, tig = lane & 3;
        const float* bias = sBias + 384;
#pragma unroll
        for (int nb = 0; nb < 4; nb++) {
            int col = ncol + nb * 8 + 2 * tig;
            float bb0 = bias[col], bb1 = bias[col + 1];
#pragma unroll
            for (int mt = 0; mt < 2; mt++) {
                int r0 = mrow + mt * 16 + gq;
                *(float2*)(sm + OFF_AHI + r0 * 272 + col * 4) =
                    make_float2(acc[nb][mt][0] + bb0, acc[nb][mt][1] + bb1);
                *(float2*)(sm + OFF_AHI + (r0 + 8) * 272 + col * 4) =
                    make_float2(acc[nb][mt][2] + bb0, acc[nb][mt][3] + bb1);
            }
        }
    }
    __syncthreads();
    // scatter: all 256 threads; two threads per edge row
    {
        int r = tid >> 1, half = tid & 1;
        const float* so = (const float*)(sm + OFF_AHI + r * 272) + half * 32;
        float* eo = edge_out + (size_t)(e0 + r) * 64 + half * 32;
#pragma unroll
        for (int q = 0; q < 8; q++) ((float4*)eo)[q] = ((const float4*)so)[q];
        float* md = g_msg + (size_t)sCol[r] * 64 + half * 32;
#pragma unroll
        for (int j = 0; j < 32; j++) atomicAdd(md + j, so[j]);
    }
}

// ---------------- node kernel ----------------
__global__ void __launch_bounds__(NTHREADS, 1)
node_kernel(const float* __restrict__ h,
            const float* __restrict__ B0, const float* __restrict__ B1,
            const float* __restrict__ B2, const float* __restrict__ B3,
            float* __restrict__ h_out)
{
    extern __shared__ unsigned char sm[];
    uint32_t sb = smem_u32(sm);
    const int tid = threadIdx.x, wid = tid >> 5, lane = tid & 31;
    const int n0 = blockIdx.x * MTILE;
    float* sBias = (float*)(sm + OFF_BIAS);

    if (tid < 128) {
        sBias[tid] = B0[tid]; sBias[128 + tid] = B1[tid]; sBias[256 + tid] = B2[tid];
        if (tid < 64) sBias[384 + tid] = B3[tid];
    }
    if (tid < 128) {
        int row = tid;
        int n = n0 + row;
        bool ok = (n < N_TOTAL);
        unsigned char* Ah = sm + OFF_AHI + row * 400;
        unsigned char* Al = sm + OFF_ALO + row * 400;
#pragma unroll
        for (int c = 0; c < 4; c++) {
            float4 v[8];
            if (ok) {
                const float4* p = (c < 2) ? (const float4*)(h + (size_t)n * 64 + 32 * c)
                                          : (const float4*)(g_msg + (size_t)n * 64 + 32 * (c - 2));
#pragma unroll
                for (int j = 0; j < 8; j++) v[j] = p[j];
            } else {
#pragma unroll
                for (int j = 0; j < 8; j++) v[j] = make_float4(0.f, 0.f, 0.f, 0.f);
            }
#pragma unroll
            for (int j = 0; j < 8; j++) {
                uint32_t h0, l0, h1, l1;
                split2(v[j].x, v[j].y, h0, l0);
                split2(v[j].z, v[j].w, h1, l1);
                int ob = c * 64 + j * 8;
                *(uint32_t*)(Ah + ob)     = h0;
                *(uint32_t*)(Ah + ob + 4) = h1;
                *(uint32_t*)(Al + ob)     = l0;
                *(uint32_t*)(Al + ob + 4) = l1;
            }
        }
    } else {
        copy16(sm + OFF_W, g_nW, 69632, tid - 128, 128);
    }
    __syncthreads();

    float acc[8][2][4];

    gemm3<128, 128>(sb, 34816, wid, lane, acc);
    __syncthreads();
    cp_async_copy(sm + OFF_W, g_nW + 69632, 69632, tid, NTHREADS); CP_COMMIT();
    epi_mid<128>(acc, sm, sBias, wid, lane);
    CP_WAIT();
    __syncthreads();

    gemm3<128, 128>(sb, 34816, wid, lane, acc);
    __syncthreads();
    cp_async_copy(sm + OFF_W, g_nW + 139264, 69632, tid, NTHREADS); CP_COMMIT();
    epi_mid<128>(acc, sm, sBias + 128, wid, lane);
    CP_WAIT();
    __syncthreads();

    gemm3<128, 128>(sb, 34816, wid, lane, acc);
    __syncthreads();
    cp_async_copy(sm + OFF_W, g_nW + 208896, 34816, tid, NTHREADS); CP_COMMIT();
    epi_mid<128>(acc, sm, sBias + 256, wid, lane);
    CP_WAIT();
    __syncthreads();

    gemm3<128, 64>(sb, 17408, wid, lane, acc);
    {
        const int mrow = (wid & 3) * 32, ncol = (wid >> 2) * 32;
        const int gq = lane >> 2, tig = lane & 3;
        const float* bias = sBias + 384;
#pragma unroll
        for (int nb = 0; nb < 4; nb++) {
            int col = ncol + nb * 8 + 2 * tig;
            float bb0 = bias[col], bb1 = bias[col + 1];
#pragma unroll
            for (int mt = 0; mt < 2; mt++) {
                int r = n0 + mrow + mt * 16 + gq;
                if (r < N_TOTAL)
                    *(float2*)(h_out + (size_t)r * 64 + col) =
                        make_float2(acc[nb][mt][0] + bb0, acc[nb][mt][1] + bb1);
                int r2 = r + 8;
                if (r2 < N_TOTAL)
                    *(float2*)(h_out + (size_t)r2 * 64 + col) =
                        make_float2(acc[nb][mt][2] + bb0, acc[nb][mt][3] + bb1);
            }
        }
    }
}

// ---------------- host ----------------
extern "C" void kernel_launch(void* const* d_in, const int* in_sizes, int n_in,
                              void* d_out, int out_size)
{
    const float* h     = (const float*)d_in[0];
    const void*  eidx  = d_in[1];
    const float* eattr = (const float*)d_in[2];
    const float* ew0 = (const float*)d_in[3],  *eb0 = (const float*)d_in[4];
    const float* nw0 = (const float*)d_in[5],  *nb0 = (const float*)d_in[6];
    const float* ew1 = (const float*)d_in[7],  *eb1 = (const float*)d_in[8];
    const float* nw1 = (const float*)d_in[9],  *nb1 = (const float*)d_in[10];
    const float* ew2 = (const float*)d_in[11], *eb2 = (const float*)d_in[12];
    const float* nw2 = (const float*)d_in[13], *nb2 = (const float*)d_in[14];
    const float* ew3 = (const float*)d_in[15], *eb3 = (const float*)d_in[16];
    const float* nw3 = (const float*)d_in[17], *nb3 = (const float*)d_in[18];

    float* out      = (float*)d_out;
    float* h_out    = out;
    float* edge_out = out + (size_t)N_TOTAL * 64;

    cudaFuncSetAttribute(edge_kernel, cudaFuncAttributeMaxDynamicSharedMemorySize, SMEM_BYTES);
    cudaFuncSetAttribute(node_kernel, cudaFuncAttributeMaxDynamicSharedMemorySize, SMEM_BYTES);

    prologue_kernel<<<128, 256>>>((const unsigned int*)eidx,
                                  ew0, ew1, ew2, ew3, nw0, nw1, nw2, nw3);

    const int NB = E_TOTAL / MTILE;       // 6250
    edge_kernel<<<NB / 2, NTHREADS, SMEM_BYTES>>>(
        h, eidx, eattr, eb0, eb1, eb2, eb3, edge_out, 0);
    edge_kernel<<<NB - NB / 2, NTHREADS, SMEM_BYTES>>>(
        h, eidx, eattr, eb0, eb1, eb2, eb3, edge_out, NB / 2);
    node_kernel<<<(N_TOTAL + MTILE - 1) / MTILE, NTHREADS, SMEM_BYTES>>>(
        h, nb0, nb1, nb2, nb3, h_out);
}

// round 8
// speedup vs baseline: 4.5088x; 1.0281x over previous
#include <cuda_runtime.h>
#include <cuda_bf16.h>
#include <cstdint>

#define E_TOTAL 800000
#define N_TOTAL 50000
#define MTILE 128
#define NTHREADS 512

// ---------------- SMEM byte layout ----------------
#define OFF_AHI  0
#define OFF_ALO  51200
#define OFF_W    102400    // hi plane then lo plane
#define OFF_BIAS 204800
#define OFF_IDX  206848
#define SMEM_BYTES 207872

// ---------------- device globals ----------------
__device__ float g_msg[N_TOTAL * 64];
__device__ int   g_idx_is64;
// bf16 hi/lo weight planes, transposed [N][K+8]
__device__ __align__(16) unsigned char g_eW[276480]; // L0@0 L1@102400 L2@172032 L3@241664
__device__ __align__(16) unsigned char g_nW[243712]; // L0@0 L1@69632 L2@139264 L3@208896

// ---------------- helpers ----------------
__device__ __forceinline__ uint32_t smem_u32(const void* p) {
    uint32_t a;
    asm("{ .reg .u64 t; cvta.to.shared.u64 t, %1; cvt.u32.u64 %0, t; }" : "=r"(a) : "l"(p));
    return a;
}
#define LDMX4(r, a)                                                              \
    asm volatile("ldmatrix.sync.aligned.m8n8.x4.shared.b16 {%0,%1,%2,%3}, [%4];" \
        : "=r"((r)[0]), "=r"((r)[1]), "=r"((r)[2]), "=r"((r)[3]) : "r"(a))
#define LDMX2(b0, b1, a)                                                         \
    asm volatile("ldmatrix.sync.aligned.m8n8.x2.shared.b16 {%0,%1}, [%2];"       \
        : "=r"(b0), "=r"(b1) : "r"(a))
#define CP_ASYNC16(sa, g)                                                        \
    asm volatile("cp.async.cg.shared.global [%0], [%1], 16;" :: "r"(sa), "l"(g))
#define CP_COMMIT() asm volatile("cp.async.commit_group;" ::: "memory")
#define CP_WAIT()   asm volatile("cp.async.wait_group 0;" ::: "memory")

__device__ __forceinline__ void mma_bf16(float* c, uint32_t a0, uint32_t a1,
                                         uint32_t a2, uint32_t a3,
                                         uint32_t b0, uint32_t b1) {
    asm volatile(
        "mma.sync.aligned.m16n8k16.row.col.f32.bf16.bf16.f32 "
        "{%0,%1,%2,%3}, {%4,%5,%6,%7}, {%8,%9}, {%0,%1,%2,%3};"
        : "+f"(c[0]), "+f"(c[1]), "+f"(c[2]), "+f"(c[3])
        : "r"(a0), "r"(a1), "r"(a2), "r"(a3), "r"(b0), "r"(b1));
}

__device__ __forceinline__ void split2(float f0, float f1, uint32_t& hi, uint32_t& lo) {
    __nv_bfloat162 h = __floats2bfloat162_rn(f0, f1);
    float r0 = f0 - __bfloat162float(h.x);
    float r1 = f1 - __bfloat162float(h.y);
    __nv_bfloat162 l = __floats2bfloat162_rn(r0, r1);
    hi = *reinterpret_cast<uint32_t*>(&h);
    lo = *reinterpret_cast<uint32_t*>(&l);
}

__device__ __forceinline__ void copy16(unsigned char* dst, const unsigned char* src,
                                       int bytes, int t, int nt) {
    const int4* s = (const int4*)src;
    int4* d = (int4*)dst;
    int n = bytes >> 4;
    for (int i = t; i < n; i += nt) d[i] = s[i];
}
__device__ __forceinline__ void cp_async_copy(unsigned char* dstS, const unsigned char* src,
                                              int bytes, int t, int nt) {
    uint32_t d = smem_u32(dstS);
    for (int i = t * 16; i < bytes; i += nt * 16)
        CP_ASYNC16(d + (uint32_t)i, src + i);
}

// ---------------- fused prologue ----------------
__device__ __forceinline__ void convert_one(const float* __restrict__ W,
                                            unsigned char* base, int N, int K,
                                            int g, int NT) {
    int PW = K + 8;
    int planeB = N * PW * 2;
    int total = N * K;
    for (int i = g; i < total; i += NT) {
        int n = i % N, k = i / N;
        float w = W[(size_t)k * N + n];
        __nv_bfloat16 hb = __float2bfloat16(w);
        float rem = w - __bfloat162float(hb);
        __nv_bfloat16 lb = __float2bfloat16(rem);
        *(__nv_bfloat16*)(base + n * PW * 2 + k * 2) = hb;
        *(__nv_bfloat16*)(base + planeB + n * PW * 2 + k * 2) = lb;
    }
}

__global__ void prologue_kernel(const unsigned int* __restrict__ raw,
                                const float* __restrict__ ew0, const float* __restrict__ ew1,
                                const float* __restrict__ ew2, const float* __restrict__ ew3,
                                const float* __restrict__ nw0, const float* __restrict__ nw1,
                                const float* __restrict__ nw2, const float* __restrict__ nw3)
{
    const int tid = threadIdx.x;
    const int g = blockIdx.x * blockDim.x + tid;
    const int NT = gridDim.x * blockDim.x;

    if (blockIdx.x == 0) {
        __shared__ int s_ok;
        if (tid == 0) s_ok = 1;
        __syncthreads();
        int bad = 0;
#pragma unroll
        for (int j = 0; j < 4; j++)
            if (raw[2 * (tid * 4 + j) + 1] != 0u) bad = 1;
        if (bad) s_ok = 0;
        __syncthreads();
        if (tid == 0) g_idx_is64 = s_ok;
    }

    float4* m4 = (float4*)g_msg;
    float4 z = make_float4(0.f, 0.f, 0.f, 0.f);
    for (int i = g; i < N_TOTAL * 16; i += NT) m4[i] = z;

    convert_one(ew0, g_eW + 0,      128, 192, g, NT);
    convert_one(ew1, g_eW + 102400, 128, 128, g, NT);
    convert_one(ew2, g_eW + 172032, 128, 128, g, NT);
    convert_one(ew3, g_eW + 241664,  64, 128, g, NT);
    convert_one(nw0, g_nW + 0,      128, 128, g, NT);
    convert_one(nw1, g_nW + 69632,  128, 128, g, NT);
    convert_one(nw2, g_nW + 139264, 128, 128, g, NT);
    convert_one(nw3, g_nW + 208896,  64, 128, g, NT);
}

// ---------------- GEMM: acc = Ahi*Whi + Alo*Whi + Ahi*Wlo ----------------
// Warp grid 4(m) x 4(n): warp owns 32 rows x N/4 cols.
template<int K, int N>
__device__ __forceinline__ void gemm3(uint32_t sb, int planeB, int wid, int lane,
                                      float acc[][2][4]) {
    constexpr int PWB = (K + 8) * 2;
    constexpr int NBW = N / 32;           // 8-col blocks per warp
    const int mrow = (wid & 3) * 32;
    const int ncol = (wid >> 2) * (N / 4);

#pragma unroll
    for (int nb = 0; nb < NBW; nb++)
#pragma unroll
        for (int mt = 0; mt < 2; mt++)
#pragma unroll
            for (int i = 0; i < 4; i++) acc[nb][mt][i] = 0.0f;

    const uint32_t aRowOff = (uint32_t)(mrow + (lane & 15)) * 400 + ((lane >> 4) << 4);
    const uint32_t bRowOff = (uint32_t)(ncol + (lane & 7)) * PWB + (((lane >> 3) & 1) << 4);
    const uint32_t WbH = sb + OFF_W + bRowOff;
    const uint32_t WbL = WbH + (uint32_t)planeB;

#pragma unroll 2
    for (int kc = 0; kc < K / 16; kc++) {
        uint32_t acol = kc * 32;
        uint32_t ah[8], al[8];
        LDMX4(ah,     sb + OFF_AHI + aRowOff + acol);
        LDMX4(ah + 4, sb + OFF_AHI + aRowOff + acol + 6400);
        LDMX4(al,     sb + OFF_ALO + aRowOff + acol);
        LDMX4(al + 4, sb + OFF_ALO + aRowOff + acol + 6400);
#pragma unroll
        for (int nb = 0; nb < NBW; nb++) {
            uint32_t boff = (uint32_t)nb * 8 * PWB + kc * 32;
            uint32_t bh0, bh1, bl0, bl1;
            LDMX2(bh0, bh1, WbH + boff);
            LDMX2(bl0, bl1, WbL + boff);
            mma_bf16(acc[nb][0], ah[0], ah[1], ah[2], ah[3], bh0, bh1);
            mma_bf16(acc[nb][1], ah[4], ah[5], ah[6], ah[7], bh0, bh1);
            mma_bf16(acc[nb][0], al[0], al[1], al[2], al[3], bh0, bh1);
            mma_bf16(acc[nb][1], al[4], al[5], al[6], al[7], bh0, bh1);
            mma_bf16(acc[nb][0], ah[0], ah[1], ah[2], ah[3], bl0, bl1);
            mma_bf16(acc[nb][1], ah[4], ah[5], ah[6], ah[7], bl0, bl1);
        }
    }
}

// mid-layer epilogue: bias + relu + split -> next A hi/lo planes
template<int N>
__device__ __forceinline__ void epi_mid(float acc[][2][4], unsigned char* sm,
                                        const float* bias, int wid, int lane) {
    constexpr int NBW = N / 32;
    const int mrow = (wid & 3) * 32;
    const int ncol = (wid >> 2) * (N / 4);
    const int gq = lane >> 2, tig = lane & 3;
#pragma unroll
    for (int nb = 0; nb < NBW; nb++) {
        int col = ncol + nb * 8 + 2 * tig;
        float bb0 = bias[col], bb1 = bias[col + 1];
#pragma unroll
        for (int mt = 0; mt < 2; mt++) {
            int r0 = mrow + mt * 16 + gq;
            uint32_t hi, lo;
            float f0 = fmaxf(acc[nb][mt][0] + bb0, 0.0f);
            float f1 = fmaxf(acc[nb][mt][1] + bb1, 0.0f);
            split2(f0, f1, hi, lo);
            *(uint32_t*)(sm + OFF_AHI + r0 * 400 + col * 2) = hi;
            *(uint32_t*)(sm + OFF_ALO + r0 * 400 + col * 2) = lo;
            f0 = fmaxf(acc[nb][mt][2] + bb0, 0.0f);
            f1 = fmaxf(acc[nb][mt][3] + bb1, 0.0f);
            split2(f0, f1, hi, lo);
            *(uint32_t*)(sm + OFF_AHI + (r0 + 8) * 400 + col * 2) = hi;
            *(uint32_t*)(sm + OFF_ALO + (r0 + 8) * 400 + col * 2) = lo;
        }
    }
}

// ---------------- edge kernel ----------------
__global__ void __launch_bounds__(NTHREADS, 1)
edge_kernel(const float* __restrict__ h, const void* __restrict__ eidx_raw,
            const float* __restrict__ eattr,
            const float* __restrict__ B0, const float* __restrict__ B1,
            const float* __restrict__ B2, const float* __restrict__ B3,
            float* __restrict__ edge_out, int blkoff)
{
    extern __shared__ unsigned char sm[];
    uint32_t sb = smem_u32(sm);
    const int tid = threadIdx.x, wid = tid >> 5, lane = tid & 31;
    const int e0 = (blockIdx.x + blkoff) * MTILE;
    float* sBias = (float*)(sm + OFF_BIAS);
    int* sRow = (int*)(sm + OFF_IDX);
    int* sCol = sRow + 128;

    if (tid < 128) {
        sBias[tid] = B0[tid]; sBias[128 + tid] = B1[tid]; sBias[256 + tid] = B2[tid];
        if (tid < 64) sBias[384 + tid] = B3[tid];
        if (g_idx_is64) {
            const long long* e64 = (const long long*)eidx_raw;
            sRow[tid] = (int)e64[e0 + tid];
            sCol[tid] = (int)e64[E_TOTAL + e0 + tid];
        } else {
            const int* e32 = (const int*)eidx_raw;
            sRow[tid] = e32[e0 + tid];
            sCol[tid] = e32[E_TOTAL + e0 + tid];
        }
    }
    __syncthreads();

    if (tid < 128) {
        int row = tid;
        int hr = sRow[row], hc = sCol[row];
        unsigned char* Ah = sm + OFF_AHI + row * 400;
        unsigned char* Al = sm + OFF_ALO + row * 400;
#pragma unroll
        for (int c = 0; c < 6; c++) {
            const float4* p = (c < 2) ? (const float4*)(h + (size_t)hr * 64 + 32 * c)
                            : (c < 4) ? (const float4*)(h + (size_t)hc * 64 + 32 * (c - 2))
                                      : (const float4*)(eattr + (size_t)(e0 + row) * 64 + 32 * (c - 4));
#pragma unroll
            for (int j = 0; j < 8; j++) {
                float4 v = p[j];
                uint32_t h0, l0, h1, l1;
                split2(v.x, v.y, h0, l0);
                split2(v.z, v.w, h1, l1);
                int ob = c * 64 + j * 8;
                *(uint32_t*)(Ah + ob)     = h0;
                *(uint32_t*)(Ah + ob + 4) = h1;
                *(uint32_t*)(Al + ob)     = l0;
                *(uint32_t*)(Al + ob + 4) = l1;
            }
        }
    } else {
        copy16(sm + OFF_W, g_eW, 102400, tid - 128, NTHREADS - 128);
    }
    __syncthreads();

    float acc[4][2][4];

    gemm3<192, 128>(sb, 51200, wid, lane, acc);
    __syncthreads();
    cp_async_copy(sm + OFF_W, g_eW + 102400, 69632, tid, NTHREADS); CP_COMMIT();
    epi_mid<128>(acc, sm, sBias, wid, lane);
    CP_WAIT();
    __syncthreads();

    gemm3<128, 128>(sb, 34816, wid, lane, acc);
    __syncthreads();
    cp_async_copy(sm + OFF_W, g_eW + 172032, 69632, tid, NTHREADS); CP_COMMIT();
    epi_mid<128>(acc, sm, sBias + 128, wid, lane);
    CP_WAIT();
    __syncthreads();

    gemm3<128, 128>(sb, 34816, wid, lane, acc);
    __syncthreads();
    cp_async_copy(sm + OFF_W, g_eW + 241664, 34816, tid, NTHREADS); CP_COMMIT();
    epi_mid<128>(acc, sm, sBias + 256, wid, lane);
    CP_WAIT();
    __syncthreads();

    gemm3<128, 64>(sb, 17408, wid, lane, acc);
    __syncthreads();
    // final: bias, stage fp32 out tile (pitch 272B) in A region
    {
        const int mrow = (wid & 3) * 32, ncol = (wid >> 2) * 16;
        const int gq = lane >> 2, tig = lane & 3;
        const float* bias = sBias + 384;
#pragma unroll
        for (int nb = 0; nb < 2; nb++) {
            int col = ncol + nb * 8 + 2 * tig;
            float bb0 = bias[col], bb1 = bias[col + 1];
#pragma unroll
            for (int mt = 0; mt < 2; mt++) {
                int r0 = mrow + mt * 16 + gq;
                *(float2*)(sm + OFF_AHI + r0 * 272 + col * 4) =
                    make_float2(acc[nb][mt][0] + bb0, acc[nb][mt][1] + bb1);
                *(float2*)(sm + OFF_AHI + (r0 + 8) * 272 + col * 4) =
                    make_float2(acc[nb][mt][2] + bb0, acc[nb][mt][3] + bb1);
            }
        }
    }
    __syncthreads();
    // scatter: 512 threads; four threads per edge row (16 floats each)
    {
        int r = tid >> 2, q = tid & 3;
        const float* so = (const float*)(sm + OFF_AHI + r * 272) + q * 16;
        float* eo = edge_out + (size_t)(e0 + r) * 64 + q * 16;
#pragma unroll
        for (int t = 0; t < 4; t++) ((float4*)eo)[t] = ((const float4*)so)[t];
        float* md = g_msg + (size_t)sCol[r] * 64 + q * 16;
#pragma unroll
        for (int j = 0; j < 16; j++) atomicAdd(md + j, so[j]);
    }
}

// ---------------- node kernel ----------------
__global__ void __launch_bounds__(NTHREADS, 1)
node_kernel(const float* __restrict__ h,
            const float* __restrict__ B0, const float* __restrict__ B1,
            const float* __restrict__ B2, const float* __restrict__ B3,
            float* __restrict__ h_out)
{
    extern __shared__ unsigned char sm[];
    uint32_t sb = smem_u32(sm);
    const int tid = threadIdx.x, wid = tid >> 5, lane = tid & 31;
    const int n0 = blockIdx.x * MTILE;
    float* sBias = (float*)(sm + OFF_BIAS);

    if (tid < 128) {
        sBias[tid] = B0[tid]; sBias[128 + tid] = B1[tid]; sBias[256 + tid] = B2[tid];
        if (tid < 64) sBias[384 + tid] = B3[tid];
    }
    if (tid < 128) {
        int row = tid;
        int n = n0 + row;
        bool ok = (n < N_TOTAL);
        unsigned char* Ah = sm + OFF_AHI + row * 400;
        unsigned char* Al = sm + OFF_ALO + row * 400;
#pragma unroll
        for (int c = 0; c < 4; c++) {
            float4 v[8];
            if (ok) {
                const float4* p = (c < 2) ? (const float4*)(h + (size_t)n * 64 + 32 * c)
                                          : (const float4*)(g_msg + (size_t)n * 64 + 32 * (c - 2));
#pragma unroll
                for (int j = 0; j < 8; j++) v[j] = p[j];
            } else {
#pragma unroll
                for (int j = 0; j < 8; j++) v[j] = make_float4(0.f, 0.f, 0.f, 0.f);
            }
#pragma unroll
            for (int j = 0; j < 8; j++) {
                uint32_t h0, l0, h1, l1;
                split2(v[j].x, v[j].y, h0, l0);
                split2(v[j].z, v[j].w, h1, l1);
                int ob = c * 64 + j * 8;
                *(uint32_t*)(Ah + ob)     = h0;
                *(uint32_t*)(Ah + ob + 4) = h1;
                *(uint32_t*)(Al + ob)     = l0;
                *(uint32_t*)(Al + ob + 4) = l1;
            }
        }
    } else {
        copy16(sm + OFF_W, g_nW, 69632, tid - 128, NTHREADS - 128);
    }
    __syncthreads();

    float acc[4][2][4];

    gemm3<128, 128>(sb, 34816, wid, lane, acc);
    __syncthreads();
    cp_async_copy(sm + OFF_W, g_nW + 69632, 69632, tid, NTHREADS); CP_COMMIT();
    epi_mid<128>(acc, sm, sBias, wid, lane);
    CP_WAIT();
    __syncthreads();

    gemm3<128, 128>(sb, 34816, wid, lane, acc);
    __syncthreads();
    cp_async_copy(sm + OFF_W, g_nW + 139264, 69632, tid, NTHREADS); CP_COMMIT();
    epi_mid<128>(acc, sm, sBias + 128, wid, lane);
    CP_WAIT();
    __syncthreads();

    gemm3<128, 128>(sb, 34816, wid, lane, acc);
    __syncthreads();
    cp_async_copy(sm + OFF_W, g_nW + 208896, 34816, tid, NTHREADS); CP_COMMIT();
    epi_mid<128>(acc, sm, sBias + 256, wid, lane);
    CP_WAIT();
    __syncthreads();

    gemm3<128, 64>(sb, 17408, wid, lane, acc);
    {
        const int mrow = (wid & 3) * 32, ncol = (wid >> 2) * 16;
        const int gq = lane >> 2, tig = lane & 3;
        const float* bias = sBias + 384;
#pragma unroll
        for (int nb = 0; nb < 2; nb++) {
            int col = ncol + nb * 8 + 2 * tig;
            float bb0 = bias[col], bb1 = bias[col + 1];
#pragma unroll
            for (int mt = 0; mt < 2; mt++) {
                int r = n0 + mrow + mt * 16 + gq;
                if (r < N_TOTAL)
                    *(float2*)(h_out + (size_t)r * 64 + col) =
                        make_float2(acc[nb][mt][0] + bb0, acc[nb][mt][1] + bb1);
                int r2 = r + 8;
                if (r2 < N_TOTAL)
                    *(float2*)(h_out + (size_t)r2 * 64 + col) =
                        make_float2(acc[nb][mt][2] + bb0, acc[nb][mt][3] + bb1);
            }
        }
    }
}

// ---------------- host ----------------
extern "C" void kernel_launch(void* const* d_in, const int* in_sizes, int n_in,
                              void* d_out, int out_size)
{
    const float* h     = (const float*)d_in[0];
    const void*  eidx  = d_in[1];
    const float* eattr = (const float*)d_in[2];
    const float* ew0 = (const float*)d_in[3],  *eb0 = (const float*)d_in[4];
    const float* nw0 = (const float*)d_in[5],  *nb0 = (const float*)d_in[6];
    const float* ew1 = (const float*)d_in[7],  *eb1 = (const float*)d_in[8];
    const float* nw1 = (const float*)d_in[9],  *nb1 = (const float*)d_in[10];
    const float* ew2 = (const float*)d_in[11], *eb2 = (const float*)d_in[12];
    const float* nw2 = (const float*)d_in[13], *nb2 = (const float*)d_in[14];
    const float* ew3 = (const float*)d_in[15], *eb3 = (const float*)d_in[16];
    const float* nw3 = (const float*)d_in[17], *nb3 = (const float*)d_in[18];

    float* out      = (float*)d_out;
    float* h_out    = out;
    float* edge_out = out + (size_t)N_TOTAL * 64;

    cudaFuncSetAttribute(edge_kernel, cudaFuncAttributeMaxDynamicSharedMemorySize, SMEM_BYTES);
    cudaFuncSetAttribute(node_kernel, cudaFuncAttributeMaxDynamicSharedMemorySize, SMEM_BYTES);

    prologue_kernel<<<128, 256>>>((const unsigned int*)eidx,
                                  ew0, ew1, ew2, ew3, nw0, nw1, nw2, nw3);

    const int NB = E_TOTAL / MTILE;       // 6250
    edge_kernel<<<NB / 2, NTHREADS, SMEM_BYTES>>>(
        h, eidx, eattr, eb0, eb1, eb2, eb3, edge_out, 0);
    edge_kernel<<<NB - NB / 2, NTHREADS, SMEM_BYTES>>>(
        h, eidx, eattr, eb0, eb1, eb2, eb3, edge_out, NB / 2);
    node_kernel<<<(N_TOTAL + MTILE - 1) / MTILE, NTHREADS, SMEM_BYTES>>>(
        h, nb0, nb1, nb2, nb3, h_out);
}

// round 9
// speedup vs baseline: 7.1607x; 1.5882x over previous
#include <cuda_runtime.h>
#include <cuda_fp16.h>
#include <cstdint>

#define E_TOTAL 800000
#define N_TOTAL 50000
#define MTILE 128
#define NTHREADS 256

// ---------------- SMEM byte layout (single fp16 planes) ----------------
#define OFF_A    0          // A: 128 rows x 400B pitch (up to 192 fp16 + pad)
#define OFF_W    51200      // W: up to 128 x (192+8) fp16 = 51200B
#define OFF_BIAS 102400     // 512 floats
#define OFF_IDX  104448     // row[128], col[128]
#define SMEM_BYTES 105472   // x2 CTAs = 210944 <= 227KB

// ---------------- device globals ----------------
__device__ float g_msg[N_TOTAL * 64];
__device__ int   g_idx_is64;
// fp16 weight planes, transposed [N][K+8]
__device__ __align__(16) unsigned char g_eW[138240]; // L0@0(51200) L1@51200(34816) L2@86016(34816) L3@120832(17408)
__device__ __align__(16) unsigned char g_nW[121856]; // L0@0 L1@34816 L2@69632 L3@104448

// ---------------- helpers ----------------
__device__ __forceinline__ uint32_t smem_u32(const void* p) {
    uint32_t a;
    asm("{ .reg .u64 t; cvta.to.shared.u64 t, %1; cvt.u32.u64 %0, t; }" : "=r"(a) : "l"(p));
    return a;
}
#define LDMX4(r, a)                                                              \
    asm volatile("ldmatrix.sync.aligned.m8n8.x4.shared.b16 {%0,%1,%2,%3}, [%4];" \
        : "=r"((r)[0]), "=r"((r)[1]), "=r"((r)[2]), "=r"((r)[3]) : "r"(a))
#define LDMX2(b0, b1, a)                                                         \
    asm volatile("ldmatrix.sync.aligned.m8n8.x2.shared.b16 {%0,%1}, [%2];"       \
        : "=r"(b0), "=r"(b1) : "r"(a))
#define CP_ASYNC16(sa, g)                                                        \
    asm volatile("cp.async.cg.shared.global [%0], [%1], 16;" :: "r"(sa), "l"(g))
#define CP_COMMIT() asm volatile("cp.async.commit_group;" ::: "memory")
#define CP_WAIT()   asm volatile("cp.async.wait_group 0;" ::: "memory")

__device__ __forceinline__ void mma_f16(float* c, uint32_t a0, uint32_t a1,
                                        uint32_t a2, uint32_t a3,
                                        uint32_t b0, uint32_t b1) {
    asm volatile(
        "mma.sync.aligned.m16n8k16.row.col.f32.f16.f16.f32 "
        "{%0,%1,%2,%3}, {%4,%5,%6,%7}, {%8,%9}, {%0,%1,%2,%3};"
        : "+f"(c[0]), "+f"(c[1]), "+f"(c[2]), "+f"(c[3])
        : "r"(a0), "r"(a1), "r"(a2), "r"(a3), "r"(b0), "r"(b1));
}

__device__ __forceinline__ uint32_t pack_h2(float f0, float f1) {
    __half2 h = __floats2half2_rn(f0, f1);
    return *reinterpret_cast<uint32_t*>(&h);
}

__device__ __forceinline__ void copy16(unsigned char* dst, const unsigned char* src,
                                       int bytes, int t, int nt) {
    const int4* s = (const int4*)src;
    int4* d = (int4*)dst;
    int n = bytes >> 4;
    for (int i = t; i < n; i += nt) d[i] = s[i];
}
__device__ __forceinline__ void cp_async_copy(unsigned char* dstS, const unsigned char* src,
                                              int bytes, int t, int nt) {
    uint32_t d = smem_u32(dstS);
    for (int i = t * 16; i < bytes; i += nt * 16)
        CP_ASYNC16(d + (uint32_t)i, src + i);
}

// ---------------- fused prologue ----------------
__device__ __forceinline__ void convert_one(const float* __restrict__ W,
                                            unsigned char* base, int N, int K,
                                            int g, int NT) {
    int PW = K + 8;
    int total = N * K;
    for (int i = g; i < total; i += NT) {
        int n = i % N, k = i / N;
        *(__half*)(base + n * PW * 2 + k * 2) = __float2half_rn(W[(size_t)k * N + n]);
    }
}

__global__ void prologue_kernel(const unsigned int* __restrict__ raw,
                                const float* __restrict__ ew0, const float* __restrict__ ew1,
                                const float* __restrict__ ew2, const float* __restrict__ ew3,
                                const float* __restrict__ nw0, const float* __restrict__ nw1,
                                const float* __restrict__ nw2, const float* __restrict__ nw3)
{
    const int tid = threadIdx.x;
    const int g = blockIdx.x * blockDim.x + tid;
    const int NT = gridDim.x * blockDim.x;

    if (blockIdx.x == 0) {
        __shared__ int s_ok;
        if (tid == 0) s_ok = 1;
        __syncthreads();
        int bad = 0;
#pragma unroll
        for (int j = 0; j < 4; j++)
            if (raw[2 * (tid * 4 + j) + 1] != 0u) bad = 1;
        if (bad) s_ok = 0;
        __syncthreads();
        if (tid == 0) g_idx_is64 = s_ok;
    }

    float4* m4 = (float4*)g_msg;
    float4 z = make_float4(0.f, 0.f, 0.f, 0.f);
    for (int i = g; i < N_TOTAL * 16; i += NT) m4[i] = z;

    convert_one(ew0, g_eW + 0,      128, 192, g, NT);
    convert_one(ew1, g_eW + 51200,  128, 128, g, NT);
    convert_one(ew2, g_eW + 86016,  128, 128, g, NT);
    convert_one(ew3, g_eW + 120832,  64, 128, g, NT);
    convert_one(nw0, g_nW + 0,      128, 128, g, NT);
    convert_one(nw1, g_nW + 34816,  128, 128, g, NT);
    convert_one(nw2, g_nW + 69632,  128, 128, g, NT);
    convert_one(nw3, g_nW + 104448,  64, 128, g, NT);
}

// ---------------- single-pass fp16 GEMM ----------------
// Warp grid 4(m) x 2(n): warp owns 32 rows x N/2 cols. NBW = N/16 blocks of 8.
template<int K, int N>
__device__ __forceinline__ void gemm1(uint32_t sb, int wid, int lane,
                                      float acc[][2][4]) {
    constexpr int PWB = (K + 8) * 2;
    constexpr int NBW = N / 16;
    const int mrow = (wid & 3) * 32;
    const int ncol = (wid >> 2) * (N / 2);

#pragma unroll
    for (int nb = 0; nb < NBW; nb++)
#pragma unroll
        for (int mt = 0; mt < 2; mt++)
#pragma unroll
            for (int i = 0; i < 4; i++) acc[nb][mt][i] = 0.0f;

    const uint32_t aRowOff = (uint32_t)(mrow + (lane & 15)) * 400 + ((lane >> 4) << 4);
    const uint32_t bRowOff = (uint32_t)(ncol + (lane & 7)) * PWB + (((lane >> 3) & 1) << 4);
    const uint32_t Wb = sb + OFF_W + bRowOff;

#pragma unroll 2
    for (int kc = 0; kc < K / 16; kc++) {
        uint32_t acol = kc * 32;
        uint32_t a[8];
        LDMX4(a,     sb + OFF_A + aRowOff + acol);
        LDMX4(a + 4, sb + OFF_A + aRowOff + acol + 6400);
#pragma unroll
        for (int nb = 0; nb < NBW; nb++) {
            uint32_t b0, b1;
            LDMX2(b0, b1, Wb + (uint32_t)nb * 8 * PWB + acol);
            mma_f16(acc[nb][0], a[0], a[1], a[2], a[3], b0, b1);
            mma_f16(acc[nb][1], a[4], a[5], a[6], a[7], b0, b1);
        }
    }
}

// mid-layer epilogue: bias + relu -> fp16 A plane
template<int N>
__device__ __forceinline__ void epi_mid(float acc[][2][4], unsigned char* sm,
                                        const float* bias, int wid, int lane) {
    constexpr int NBW = N / 16;
    const int mrow = (wid & 3) * 32;
    const int ncol = (wid >> 2) * (N / 2);
    const int gq = lane >> 2, tig = lane & 3;
#pragma unroll
    for (int nb = 0; nb < NBW; nb++) {
        int col = ncol + nb * 8 + 2 * tig;
        float bb0 = bias[col], bb1 = bias[col + 1];
#pragma unroll
        for (int mt = 0; mt < 2; mt++) {
            int r0 = mrow + mt * 16 + gq;
            *(uint32_t*)(sm + OFF_A + r0 * 400 + col * 2) =
                pack_h2(fmaxf(acc[nb][mt][0] + bb0, 0.0f),
                        fmaxf(acc[nb][mt][1] + bb1, 0.0f));
            *(uint32_t*)(sm + OFF_A + (r0 + 8) * 400 + col * 2) =
                pack_h2(fmaxf(acc[nb][mt][2] + bb0, 0.0f),
                        fmaxf(acc[nb][mt][3] + bb1, 0.0f));
        }
    }
}

// ---------------- edge kernel ----------------
__global__ void __launch_bounds__(NTHREADS, 2)
edge_kernel(const float* __restrict__ h, const void* __restrict__ eidx_raw,
            const float* __restrict__ eattr,
            const float* __restrict__ B0, const float* __restrict__ B1,
            const float* __restrict__ B2, const float* __restrict__ B3,
            float* __restrict__ edge_out, int blkoff)
{
    extern __shared__ unsigned char sm[];
    uint32_t sb = smem_u32(sm);
    const int tid = threadIdx.x, wid = tid >> 5, lane = tid & 31;
    const int e0 = (blockIdx.x + blkoff) * MTILE;
    float* sBias = (float*)(sm + OFF_BIAS);
    int* sRow = (int*)(sm + OFF_IDX);
    int* sCol = sRow + 128;

    if (tid < 128) {
        sBias[tid] = B0[tid]; sBias[128 + tid] = B1[tid]; sBias[256 + tid] = B2[tid];
        if (tid < 64) sBias[384 + tid] = B3[tid];
        if (g_idx_is64) {
            const long long* e64 = (const long long*)eidx_raw;
            sRow[tid] = (int)e64[e0 + tid];
            sCol[tid] = (int)e64[E_TOTAL + e0 + tid];
        } else {
            const int* e32 = (const int*)eidx_raw;
            sRow[tid] = e32[e0 + tid];
            sCol[tid] = e32[E_TOTAL + e0 + tid];
        }
    }
    __syncthreads();

    // gather (tid<128) overlapped with W0 staging (tid>=128)
    if (tid < 128) {
        int row = tid;
        int hr = sRow[row], hc = sCol[row];
        unsigned char* Ap = sm + OFF_A + row * 400;
#pragma unroll
        for (int c = 0; c < 6; c++) {
            const float4* p = (c < 2) ? (const float4*)(h + (size_t)hr * 64 + 32 * c)
                            : (c < 4) ? (const float4*)(h + (size_t)hc * 64 + 32 * (c - 2))
                                      : (const float4*)(eattr + (size_t)(e0 + row) * 64 + 32 * (c - 4));
#pragma unroll
            for (int j = 0; j < 8; j++) {
                float4 v = p[j];
                *(uint32_t*)(Ap + c * 64 + j * 8)     = pack_h2(v.x, v.y);
                *(uint32_t*)(Ap + c * 64 + j * 8 + 4) = pack_h2(v.z, v.w);
            }
        }
    } else {
        copy16(sm + OFF_W, g_eW, 51200, tid - 128, NTHREADS - 128);
    }
    __syncthreads();

    float acc[8][2][4];

    gemm1<192, 128>(sb, wid, lane, acc);
    __syncthreads();
    cp_async_copy(sm + OFF_W, g_eW + 51200, 34816, tid, NTHREADS); CP_COMMIT();
    epi_mid<128>(acc, sm, sBias, wid, lane);
    CP_WAIT();
    __syncthreads();

    gemm1<128, 128>(sb, wid, lane, acc);
    __syncthreads();
    cp_async_copy(sm + OFF_W, g_eW + 86016, 34816, tid, NTHREADS); CP_COMMIT();
    epi_mid<128>(acc, sm, sBias + 128, wid, lane);
    CP_WAIT();
    __syncthreads();

    gemm1<128, 128>(sb, wid, lane, acc);
    __syncthreads();
    cp_async_copy(sm + OFF_W, g_eW + 120832, 17408, tid, NTHREADS); CP_COMMIT();
    epi_mid<128>(acc, sm, sBias + 256, wid, lane);
    CP_WAIT();
    __syncthreads();

    gemm1<128, 64>(sb, wid, lane, acc);
    __syncthreads();
    // final: bias, stage fp32 out tile (pitch 272B) in A region
    {
        const int mrow = (wid & 3) * 32, ncol = (wid >> 2) * 32;
        const int gq = lane >> 2, tig = lane & 3;
        const float* bias = sBias + 384;
#pragma unroll
        for (int nb = 0; nb < 4; nb++) {
            int col = ncol + nb * 8 + 2 * tig;
            float bb0 = bias[col], bb1 = bias[col + 1];
#pragma unroll
            for (int mt = 0; mt < 2; mt++) {
                int r0 = mrow + mt * 16 + gq;
                *(float2*)(sm + OFF_A + r0 * 272 + col * 4) =
                    make_float2(acc[nb][mt][0] + bb0, acc[nb][mt][1] + bb1);
                *(float2*)(sm + OFF_A + (r0 + 8) * 272 + col * 4) =
                    make_float2(acc[nb][mt][2] + bb0, acc[nb][mt][3] + bb1);
            }
        }
    }
    __syncthreads();
    // scatter: 256 threads; two threads per edge row (32 floats each)
    {
        int r = tid >> 1, q = tid & 1;
        const float* so = (const float*)(sm + OFF_A + r * 272) + q * 32;
        float* eo = edge_out + (size_t)(e0 + r) * 64 + q * 32;
#pragma unroll
        for (int t = 0; t < 8; t++) ((float4*)eo)[t] = ((const float4*)so)[t];
        float* md = g_msg + (size_t)sCol[r] * 64 + q * 32;
#pragma unroll
        for (int j = 0; j < 32; j++) atomicAdd(md + j, so[j]);
    }
}

// ---------------- node kernel ----------------
__global__ void __launch_bounds__(NTHREADS, 2)
node_kernel(const float* __restrict__ h,
            const float* __restrict__ B0, const float* __restrict__ B1,
            const float* __restrict__ B2, const float* __restrict__ B3,
            float* __restrict__ h_out)
{
    extern __shared__ unsigned char sm[];
    uint32_t sb = smem_u32(sm);
    const int tid = threadIdx.x, wid = tid >> 5, lane = tid & 31;
    const int n0 = blockIdx.x * MTILE;
    float* sBias = (float*)(sm + OFF_BIAS);

    if (tid < 128) {
        sBias[tid] = B0[tid]; sBias[128 + tid] = B1[tid]; sBias[256 + tid] = B2[tid];
        if (tid < 64) sBias[384 + tid] = B3[tid];
    }
    if (tid < 128) {
        int row = tid;
        int n = n0 + row;
        bool ok = (n < N_TOTAL);
        unsigned char* Ap = sm + OFF_A + row * 400;
#pragma unroll
        for (int c = 0; c < 4; c++) {
            float4 v[8];
            if (ok) {
                const float4* p = (c < 2) ? (const float4*)(h + (size_t)n * 64 + 32 * c)
                                          : (const float4*)(g_msg + (size_t)n * 64 + 32 * (c - 2));
#pragma unroll
                for (int j = 0; j < 8; j++) v[j] = p[j];
            } else {
#pragma unroll
                for (int j = 0; j < 8; j++) v[j] = make_float4(0.f, 0.f, 0.f, 0.f);
            }
#pragma unroll
            for (int j = 0; j < 8; j++) {
                *(uint32_t*)(Ap + c * 64 + j * 8)     = pack_h2(v[j].x, v[j].y);
                *(uint32_t*)(Ap + c * 64 + j * 8 + 4) = pack_h2(v[j].z, v[j].w);
            }
        }
    } else {
        copy16(sm + OFF_W, g_nW, 34816, tid - 128, NTHREADS - 128);
    }
    __syncthreads();

    float acc[8][2][4];

    gemm1<128, 128>(sb, wid, lane, acc);
    __syncthreads();
    cp_async_copy(sm + OFF_W, g_nW + 34816, 34816, tid, NTHREADS); CP_COMMIT();
    epi_mid<128>(acc, sm, sBias, wid, lane);
    CP_WAIT();
    __syncthreads();

    gemm1<128, 128>(sb, wid, lane, acc);
    __syncthreads();
    cp_async_copy(sm + OFF_W, g_nW + 69632, 34816, tid, NTHREADS); CP_COMMIT();
    epi_mid<128>(acc, sm, sBias + 128, wid, lane);
    CP_WAIT();
    __syncthreads();

    gemm1<128, 128>(sb, wid, lane, acc);
    __syncthreads();
    cp_async_copy(sm + OFF_W, g_nW + 104448, 17408, tid, NTHREADS); CP_COMMIT();
    epi_mid<128>(acc, sm, sBias + 256, wid, lane);
    CP_WAIT();
    __syncthreads();

    gemm1<128, 64>(sb, wid, lane, acc);
    {
        const int mrow = (wid & 3) * 32, ncol = (wid >> 2) * 32;
        const int gq = lane >> 2, tig = lane & 3;
        const float* bias = sBias + 384;
#pragma unroll
        for (int nb = 0; nb < 4; nb++) {
            int col = ncol + nb * 8 + 2 * tig;
            float bb0 = bias[col], bb1 = bias[col + 1];
#pragma unroll
            for (int mt = 0; mt < 2; mt++) {
                int r = n0 + mrow + mt * 16 + gq;
                if (r < N_TOTAL)
                    *(float2*)(h_out + (size_t)r * 64 + col) =
                        make_float2(acc[nb][mt][0] + bb0, acc[nb][mt][1] + bb1);
                int r2 = r + 8;
                if (r2 < N_TOTAL)
                    *(float2*)(h_out + (size_t)r2 * 64 + col) =
                        make_float2(acc[nb][mt][2] + bb0, acc[nb][mt][3] + bb1);
            }
        }
    }
}

// ---------------- host ----------------
extern "C" void kernel_launch(void* const* d_in, const int* in_sizes, int n_in,
                              void* d_out, int out_size)
{
    const float* h     = (const float*)d_in[0];
    const void*  eidx  = d_in[1];
    const float* eattr = (const float*)d_in[2];
    const float* ew0 = (const float*)d_in[3],  *eb0 = (const float*)d_in[4];
    const float* nw0 = (const float*)d_in[5],  *nb0 = (const float*)d_in[6];
    const float* ew1 = (const float*)d_in[7],  *eb1 = (const float*)d_in[8];
    const float* nw1 = (const float*)d_in[9],  *nb1 = (const float*)d_in[10];
    const float* ew2 = (const float*)d_in[11], *eb2 = (const float*)d_in[12];
    const float* nw2 = (const float*)d_in[13], *nb2 = (const float*)d_in[14];
    const float* ew3 = (const float*)d_in[15], *eb3 = (const float*)d_in[16];
    const float* nw3 = (const float*)d_in[17], *nb3 = (const float*)d_in[18];

    float* out      = (float*)d_out;
    float* h_out    = out;
    float* edge_out = out + (size_t)N_TOTAL * 64;

    cudaFuncSetAttribute(edge_kernel, cudaFuncAttributeMaxDynamicSharedMemorySize, SMEM_BYTES);
    cudaFuncSetAttribute(node_kernel, cudaFuncAttributeMaxDynamicSharedMemorySize, SMEM_BYTES);

    prologue_kernel<<<128, 256>>>((const unsigned int*)eidx,
                                  ew0, ew1, ew2, ew3, nw0, nw1, nw2, nw3);

    const int NB = E_TOTAL / MTILE;       // 6250
    edge_kernel<<<NB / 2, NTHREADS, SMEM_BYTES>>>(
        h, eidx, eattr, eb0, eb1, eb2, eb3, edge_out, 0);
    edge_kernel<<<NB - NB / 2, NTHREADS, SMEM_BYTES>>>(
        h, eidx, eattr, eb0, eb1, eb2, eb3, edge_out, NB / 2);
    node_kernel<<<(N_TOTAL + MTILE - 1) / MTILE, NTHREADS, SMEM_BYTES>>>(
        h, nb0, nb1, nb2, nb3, h_out);
}

// round 10
// speedup vs baseline: 7.6042x; 1.0619x over previous
#include <cuda_runtime.h>
#include <cuda_fp16.h>
#include <cstdint>

#define E_TOTAL 800000
#define N_TOTAL 50000
#define MTILE 128
#define NTHREADS 256

// ---------------- SMEM byte layout (fp16 planes) ----------------
#define OFF_A    0          // A: 128 rows x 400B pitch
#define OFF_W    51200      // W: up to 128 x (192+8) fp16
#define OFF_BIAS 102400     // 512 floats
#define OFF_IDX  104448     // row[128], col[128]
#define SMEM_BYTES 105472   // x2 CTAs/SM

// ---------------- device globals ----------------
__device__ int g_idx_is64;
__device__ int g_cnt[N_TOTAL];        // static-zero; scan resets after use (replay-safe)
__device__ int g_start[N_TOTAL + 1];
__device__ int g_cursor[N_TOTAL];
__device__ int g_elist[E_TOTAL];
// fp16 weight planes, transposed [N][K+8]
__device__ __align__(16) unsigned char g_eW[138240]; // L0@0 L1@51200 L2@86016 L3@120832
__device__ __align__(16) unsigned char g_nW[121856]; // L0@0 L1@34816 L2@69632 L3@104448

// ---------------- helpers ----------------
__device__ __forceinline__ uint32_t smem_u32(const void* p) {
    uint32_t a;
    asm("{ .reg .u64 t; cvta.to.shared.u64 t, %1; cvt.u32.u64 %0, t; }" : "=r"(a) : "l"(p));
    return a;
}
#define LDMX4(r, a)                                                              \
    asm volatile("ldmatrix.sync.aligned.m8n8.x4.shared.b16 {%0,%1,%2,%3}, [%4];" \
        : "=r"((r)[0]), "=r"((r)[1]), "=r"((r)[2]), "=r"((r)[3]) : "r"(a))
#define LDMX2(b0, b1, a)                                                         \
    asm volatile("ldmatrix.sync.aligned.m8n8.x2.shared.b16 {%0,%1}, [%2];"       \
        : "=r"(b0), "=r"(b1) : "r"(a))
#define CP_ASYNC16(sa, g)                                                        \
    asm volatile("cp.async.cg.shared.global [%0], [%1], 16;" :: "r"(sa), "l"(g))
#define CP_COMMIT() asm volatile("cp.async.commit_group;" ::: "memory")
#define CP_WAIT()   asm volatile("cp.async.wait_group 0;" ::: "memory")

__device__ __forceinline__ void mma_f16(float* c, uint32_t a0, uint32_t a1,
                                        uint32_t a2, uint32_t a3,
                                        uint32_t b0, uint32_t b1) {
    asm volatile(
        "mma.sync.aligned.m16n8k16.row.col.f32.f16.f16.f32 "
        "{%0,%1,%2,%3}, {%4,%5,%6,%7}, {%8,%9}, {%0,%1,%2,%3};"
        : "+f"(c[0]), "+f"(c[1]), "+f"(c[2]), "+f"(c[3])
        : "r"(a0), "r"(a1), "r"(a2), "r"(a3), "r"(b0), "r"(b1));
}
__device__ __forceinline__ uint32_t pack_h2(float f0, float f1) {
    __half2 h = __floats2half2_rn(f0, f1);
    return *reinterpret_cast<uint32_t*>(&h);
}
__device__ __forceinline__ void copy16(unsigned char* dst, const unsigned char* src,
                                       int bytes, int t, int nt) {
    const int4* s = (const int4*)src;
    int4* d = (int4*)dst;
    int n = bytes >> 4;
    for (int i = t; i < n; i += nt) d[i] = s[i];
}
__device__ __forceinline__ void cp_async_copy(unsigned char* dstS, const unsigned char* src,
                                              int bytes, int t, int nt) {
    uint32_t d = smem_u32(dstS);
    for (int i = t * 16; i < bytes; i += nt * 16)
        CP_ASYNC16(d + (uint32_t)i, src + i);
}
__device__ __forceinline__ int load_col(const void* raw, int e) {
    if (g_idx_is64) return (int)((const long long*)raw)[E_TOTAL + e];
    return ((const int*)raw)[E_TOTAL + e];
}

// ---------------- prologue: sniff + weight convert ----------------
__device__ __forceinline__ void convert_one(const float* __restrict__ W,
                                            unsigned char* base, int N, int K,
                                            int g, int NT) {
    int PW = K + 8;
    int total = N * K;
    for (int i = g; i < total; i += NT) {
        int n = i % N, k = i / N;
        *(__half*)(base + n * PW * 2 + k * 2) = __float2half_rn(W[(size_t)k * N + n]);
    }
}

__global__ void prologue_kernel(const unsigned int* __restrict__ raw,
                                const float* __restrict__ ew0, const float* __restrict__ ew1,
                                const float* __restrict__ ew2, const float* __restrict__ ew3,
                                const float* __restrict__ nw0, const float* __restrict__ nw1,
                                const float* __restrict__ nw2, const float* __restrict__ nw3)
{
    const int tid = threadIdx.x;
    const int g = blockIdx.x * blockDim.x + tid;
    const int NT = gridDim.x * blockDim.x;

    if (blockIdx.x == 0) {
        __shared__ int s_ok;
        if (tid == 0) s_ok = 1;
        __syncthreads();
        int bad = 0;
#pragma unroll
        for (int j = 0; j < 4; j++)
            if (raw[2 * (tid * 4 + j) + 1] != 0u) bad = 1;
        if (bad) s_ok = 0;
        __syncthreads();
        if (tid == 0) g_idx_is64 = s_ok;
    }

    convert_one(ew0, g_eW + 0,      128, 192, g, NT);
    convert_one(ew1, g_eW + 51200,  128, 128, g, NT);
    convert_one(ew2, g_eW + 86016,  128, 128, g, NT);
    convert_one(ew3, g_eW + 120832,  64, 128, g, NT);
    convert_one(nw0, g_nW + 0,      128, 128, g, NT);
    convert_one(nw1, g_nW + 34816,  128, 128, g, NT);
    convert_one(nw2, g_nW + 69632,  128, 128, g, NT);
    convert_one(nw3, g_nW + 104448,  64, 128, g, NT);
}

// ---------------- CSR binning ----------------
__global__ void count_kernel(const void* __restrict__ raw) {
    int g = blockIdx.x * blockDim.x + threadIdx.x;
    int NT = gridDim.x * blockDim.x;
    for (int e = g; e < E_TOTAL; e += NT)
        atomicAdd(&g_cnt[load_col(raw, e)], 1);
}

__global__ void scan_kernel() {   // single CTA, 1024 threads
    const int t = threadIdx.x;
    const int C = (N_TOTAL + 1023) / 1024;   // 49
    const int base = t * C;
    int s = 0;
    for (int i = 0; i < C; i++) {
        int idx = base + i;
        if (idx < N_TOTAL) s += g_cnt[idx];
    }
    // block exclusive scan of s
    int lane = t & 31, w = t >> 5;
    int x = s;
#pragma unroll
    for (int o = 1; o < 32; o <<= 1) {
        int y = __shfl_up_sync(0xFFFFFFFF, x, o);
        if (lane >= o) x += y;
    }
    __shared__ int ws[32];
    if (lane == 31) ws[w] = x;
    __syncthreads();
    if (w == 0) {
        int z = ws[lane];
#pragma unroll
        for (int o = 1; o < 32; o <<= 1) {
            int y = __shfl_up_sync(0xFFFFFFFF, z, o);
            if (lane >= o) z += y;
        }
        ws[lane] = z;
    }
    __syncthreads();
    int run = (x - s) + (w > 0 ? ws[w - 1] : 0);   // exclusive prefix
    for (int i = 0; i < C; i++) {
        int idx = base + i;
        if (idx < N_TOTAL) {
            g_start[idx] = run;
            g_cursor[idx] = run;
            run += g_cnt[idx];
            g_cnt[idx] = 0;                         // reset for next replay
        }
    }
    if (t == 1023) g_start[N_TOTAL] = run;
}

__global__ void fill_kernel(const void* __restrict__ raw) {
    int g = blockIdx.x * blockDim.x + threadIdx.x;
    int NT = gridDim.x * blockDim.x;
    for (int e = g; e < E_TOTAL; e += NT) {
        int pos = atomicAdd(&g_cursor[load_col(raw, e)], 1);
        g_elist[pos] = e;
    }
}

// ---------------- single-pass fp16 GEMM ----------------
template<int K, int N>
__device__ __forceinline__ void gemm1(uint32_t sb, int wid, int lane,
                                      float acc[][2][4]) {
    constexpr int PWB = (K + 8) * 2;
    constexpr int NBW = N / 16;
    const int mrow = (wid & 3) * 32;
    const int ncol = (wid >> 2) * (N / 2);

#pragma unroll
    for (int nb = 0; nb < NBW; nb++)
#pragma unroll
        for (int mt = 0; mt < 2; mt++)
#pragma unroll
            for (int i = 0; i < 4; i++) acc[nb][mt][i] = 0.0f;

    const uint32_t aRowOff = (uint32_t)(mrow + (lane & 15)) * 400 + ((lane >> 4) << 4);
    const uint32_t bRowOff = (uint32_t)(ncol + (lane & 7)) * PWB + (((lane >> 3) & 1) << 4);
    const uint32_t Wb = sb + OFF_W + bRowOff;

#pragma unroll 2
    for (int kc = 0; kc < K / 16; kc++) {
        uint32_t acol = kc * 32;
        uint32_t a[8];
        LDMX4(a,     sb + OFF_A + aRowOff + acol);
        LDMX4(a + 4, sb + OFF_A + aRowOff + acol + 6400);
#pragma unroll
        for (int nb = 0; nb < NBW; nb++) {
            uint32_t b0, b1;
            LDMX2(b0, b1, Wb + (uint32_t)nb * 8 * PWB + acol);
            mma_f16(acc[nb][0], a[0], a[1], a[2], a[3], b0, b1);
            mma_f16(acc[nb][1], a[4], a[5], a[6], a[7], b0, b1);
        }
    }
}

template<int N>
__device__ __forceinline__ void epi_mid(float acc[][2][4], unsigned char* sm,
                                        const float* bias, int wid, int lane) {
    constexpr int NBW = N / 16;
    const int mrow = (wid & 3) * 32;
    const int ncol = (wid >> 2) * (N / 2);
    const int gq = lane >> 2, tig = lane & 3;
#pragma unroll
    for (int nb = 0; nb < NBW; nb++) {
        int col = ncol + nb * 8 + 2 * tig;
        float bb0 = bias[col], bb1 = bias[col + 1];
#pragma unroll
        for (int mt = 0; mt < 2; mt++) {
            int r0 = mrow + mt * 16 + gq;
            *(uint32_t*)(sm + OFF_A + r0 * 400 + col * 2) =
                pack_h2(fmaxf(acc[nb][mt][0] + bb0, 0.0f),
                        fmaxf(acc[nb][mt][1] + bb1, 0.0f));
            *(uint32_t*)(sm + OFF_A + (r0 + 8) * 400 + col * 2) =
                pack_h2(fmaxf(acc[nb][mt][2] + bb0, 0.0f),
                        fmaxf(acc[nb][mt][3] + bb1, 0.0f));
        }
    }
}

// ---------------- edge kernel (no atomics) ----------------
__global__ void __launch_bounds__(NTHREADS, 2)
edge_kernel(const float* __restrict__ h, const void* __restrict__ eidx_raw,
            const float* __restrict__ eattr,
            const float* __restrict__ B0, const float* __restrict__ B1,
            const float* __restrict__ B2, const float* __restrict__ B3,
            float* __restrict__ edge_out, int blkoff)
{
    extern __shared__ unsigned char sm[];
    uint32_t sb = smem_u32(sm);
    const int tid = threadIdx.x, wid = tid >> 5, lane = tid & 31;
    const int e0 = (blockIdx.x + blkoff) * MTILE;
    float* sBias = (float*)(sm + OFF_BIAS);
    int* sRow = (int*)(sm + OFF_IDX);
    int* sCol = sRow + 128;

    if (tid < 128) {
        sBias[tid] = B0[tid]; sBias[128 + tid] = B1[tid]; sBias[256 + tid] = B2[tid];
        if (tid < 64) sBias[384 + tid] = B3[tid];
        if (g_idx_is64) {
            const long long* e64 = (const long long*)eidx_raw;
            sRow[tid] = (int)e64[e0 + tid];
            sCol[tid] = (int)e64[E_TOTAL + e0 + tid];
        } else {
            const int* e32 = (const int*)eidx_raw;
            sRow[tid] = e32[e0 + tid];
            sCol[tid] = e32[E_TOTAL + e0 + tid];
        }
    }
    __syncthreads();

    if (tid < 128) {
        int row = tid;
        int hr = sRow[row], hc = sCol[row];
        unsigned char* Ap = sm + OFF_A + row * 400;
#pragma unroll
        for (int c = 0; c < 6; c++) {
            const float4* p = (c < 2) ? (const float4*)(h + (size_t)hr * 64 + 32 * c)
                            : (c < 4) ? (const float4*)(h + (size_t)hc * 64 + 32 * (c - 2))
                                      : (const float4*)(eattr + (size_t)(e0 + row) * 64 + 32 * (c - 4));
#pragma unroll
            for (int j = 0; j < 8; j++) {
                float4 v = p[j];
                *(uint32_t*)(Ap + c * 64 + j * 8)     = pack_h2(v.x, v.y);
                *(uint32_t*)(Ap + c * 64 + j * 8 + 4) = pack_h2(v.z, v.w);
            }
        }
    } else {
        copy16(sm + OFF_W, g_eW, 51200, tid - 128, NTHREADS - 128);
    }
    __syncthreads();

    float acc[8][2][4];

    gemm1<192, 128>(sb, wid, lane, acc);
    __syncthreads();
    cp_async_copy(sm + OFF_W, g_eW + 51200, 34816, tid, NTHREADS); CP_COMMIT();
    epi_mid<128>(acc, sm, sBias, wid, lane);
    CP_WAIT();
    __syncthreads();

    gemm1<128, 128>(sb, wid, lane, acc);
    __syncthreads();
    cp_async_copy(sm + OFF_W, g_eW + 86016, 34816, tid, NTHREADS); CP_COMMIT();
    epi_mid<128>(acc, sm, sBias + 128, wid, lane);
    CP_WAIT();
    __syncthreads();

    gemm1<128, 128>(sb, wid, lane, acc);
    __syncthreads();
    cp_async_copy(sm + OFF_W, g_eW + 120832, 17408, tid, NTHREADS); CP_COMMIT();
    epi_mid<128>(acc, sm, sBias + 256, wid, lane);
    CP_WAIT();
    __syncthreads();

    gemm1<128, 64>(sb, wid, lane, acc);
    // write edge_out straight from regs (no atomics, no staging)
    {
        const int mrow = (wid & 3) * 32, ncol = (wid >> 2) * 32;
        const int gq = lane >> 2, tig = lane & 3;
        const float* bias = sBias + 384;
#pragma unroll
        for (int nb = 0; nb < 4; nb++) {
            int col = ncol + nb * 8 + 2 * tig;
            float bb0 = bias[col], bb1 = bias[col + 1];
#pragma unroll
            for (int mt = 0; mt < 2; mt++) {
                int r = mrow + mt * 16 + gq;
                *(float2*)(edge_out + (size_t)(e0 + r) * 64 + col) =
                    make_float2(acc[nb][mt][0] + bb0, acc[nb][mt][1] + bb1);
                *(float2*)(edge_out + (size_t)(e0 + r + 8) * 64 + col) =
                    make_float2(acc[nb][mt][2] + bb0, acc[nb][mt][3] + bb1);
            }
        }
    }
}

// ---------------- node kernel (CSR msg gather) ----------------
__global__ void __launch_bounds__(NTHREADS, 2)
node_kernel(const float* __restrict__ h, const float* __restrict__ edge_out,
            const float* __restrict__ B0, const float* __restrict__ B1,
            const float* __restrict__ B2, const float* __restrict__ B3,
            float* __restrict__ h_out)
{
    extern __shared__ unsigned char sm[];
    uint32_t sb = smem_u32(sm);
    const int tid = threadIdx.x, wid = tid >> 5, lane = tid & 31;
    const int n0 = blockIdx.x * MTILE;
    float* sBias = (float*)(sm + OFF_BIAS);

    if (tid < 128) {
        sBias[tid] = B0[tid]; sBias[128 + tid] = B1[tid]; sBias[256 + tid] = B2[tid];
        if (tid < 64) sBias[384 + tid] = B3[tid];
    }
    // stage W0 async, then gather while it flies
    cp_async_copy(sm + OFF_W, g_nW, 34816, tid, NTHREADS); CP_COMMIT();

    // msg gather: warp per row group; lane covers cols {2*lane, 2*lane+1}
#pragma unroll 1
    for (int rr = 0; rr < 16; rr++) {
        int row = wid * 16 + rr;
        int n = n0 + row;
        float h0 = 0.f, h1 = 0.f, m0 = 0.f, m1 = 0.f;
        if (n < N_TOTAL) {
            float2 hv = *(const float2*)(h + (size_t)n * 64 + 2 * lane);
            h0 = hv.x; h1 = hv.y;
            int s = g_start[n], epos = g_start[n + 1];
            for (; s < epos; s++) {
                int e = g_elist[s];
                float2 mv = *(const float2*)(edge_out + (size_t)e * 64 + 2 * lane);
                m0 += mv.x; m1 += mv.y;
            }
        }
        unsigned char* Ap = sm + OFF_A + row * 400;
        *(uint32_t*)(Ap + 4 * lane)       = pack_h2(h0, h1);
        *(uint32_t*)(Ap + 128 + 4 * lane) = pack_h2(m0, m1);
    }
    CP_WAIT();
    __syncthreads();

    float acc[8][2][4];

    gemm1<128, 128>(sb, wid, lane, acc);
    __syncthreads();
    cp_async_copy(sm + OFF_W, g_nW + 34816, 34816, tid, NTHREADS); CP_COMMIT();
    epi_mid<128>(acc, sm, sBias, wid, lane);
    CP_WAIT();
    __syncthreads();

    gemm1<128, 128>(sb, wid, lane, acc);
    __syncthreads();
    cp_async_copy(sm + OFF_W, g_nW + 69632, 34816, tid, NTHREADS); CP_COMMIT();
    epi_mid<128>(acc, sm, sBias + 128, wid, lane);
    CP_WAIT();
    __syncthreads();

    gemm1<128, 128>(sb, wid, lane, acc);
    __syncthreads();
    cp_async_copy(sm + OFF_W, g_nW + 104448, 17408, tid, NTHREADS); CP_COMMIT();
    epi_mid<128>(acc, sm, sBias + 256, wid, lane);
    CP_WAIT();
    __syncthreads();

    gemm1<128, 64>(sb, wid, lane, acc);
    {
        const int mrow = (wid & 3) * 32, ncol = (wid >> 2) * 32;
        const int gq = lane >> 2, tig = lane & 3;
        const float* bias = sBias + 384;
#pragma unroll
        for (int nb = 0; nb < 4; nb++) {
            int col = ncol + nb * 8 + 2 * tig;
            float bb0 = bias[col], bb1 = bias[col + 1];
#pragma unroll
            for (int mt = 0; mt < 2; mt++) {
                int r = n0 + mrow + mt * 16 + gq;
                if (r < N_TOTAL)
                    *(float2*)(h_out + (size_t)r * 64 + col) =
                        make_float2(acc[nb][mt][0] + bb0, acc[nb][mt][1] + bb1);
                int r2 = r + 8;
                if (r2 < N_TOTAL)
                    *(float2*)(h_out + (size_t)r2 * 64 + col) =
                        make_float2(acc[nb][mt][2] + bb0, acc[nb][mt][3] + bb1);
            }
        }
    }
}

// ---------------- host ----------------
extern "C" void kernel_launch(void* const* d_in, const int* in_sizes, int n_in,
                              void* d_out, int out_size)
{
    const float* h     = (const float*)d_in[0];
    const void*  eidx  = d_in[1];
    const float* eattr = (const float*)d_in[2];
    const float* ew0 = (const float*)d_in[3],  *eb0 = (const float*)d_in[4];
    const float* nw0 = (const float*)d_in[5],  *nb0 = (const float*)d_in[6];
    const float* ew1 = (const float*)d_in[7],  *eb1 = (const float*)d_in[8];
    const float* nw1 = (const float*)d_in[9],  *nb1 = (const float*)d_in[10];
    const float* ew2 = (const float*)d_in[11], *eb2 = (const float*)d_in[12];
    const float* nw2 = (const float*)d_in[13], *nb2 = (const float*)d_in[14];
    const float* ew3 = (const float*)d_in[15], *eb3 = (const float*)d_in[16];
    const float* nw3 = (const float*)d_in[17], *nb3 = (const float*)d_in[18];

    float* out      = (float*)d_out;
    float* h_out    = out;
    float* edge_out = out + (size_t)N_TOTAL * 64;

    cudaFuncSetAttribute(edge_kernel, cudaFuncAttributeMaxDynamicSharedMemorySize, SMEM_BYTES);
    cudaFuncSetAttribute(node_kernel, cudaFuncAttributeMaxDynamicSharedMemorySize, SMEM_BYTES);

    prologue_kernel<<<128, 256>>>((const unsigned int*)eidx,
                                  ew0, ew1, ew2, ew3, nw0, nw1, nw2, nw3);
    count_kernel<<<128, 256>>>(eidx);
    scan_kernel<<<1, 1024>>>();
    fill_kernel<<<128, 256>>>(eidx);

    const int NB = E_TOTAL / MTILE;       // 6250
    edge_kernel<<<NB / 2, NTHREADS, SMEM_BYTES>>>(
        h, eidx, eattr, eb0, eb1, eb2, eb3, edge_out, 0);
    edge_kernel<<<NB - NB / 2, NTHREADS, SMEM_BYTES>>>(
        h, eidx, eattr, eb0, eb1, eb2, eb3, edge_out, NB / 2);
    node_kernel<<<(N_TOTAL + MTILE - 1) / MTILE, NTHREADS, SMEM_BYTES>>>(
        h, edge_out, nb0, nb1, nb2, nb3, h_out);
}